// round 9
// baseline (speedup 1.0000x reference)
#include <cuda_runtime.h>
#include <cuda_bf16.h>
#include <cstdint>

#define T_STEPS 20
#define N_NODES 32768
#define TILE_N  128
#define DH      128
#define K_TOT   192
#define NBLOCKS (N_NODES / TILE_N)   // 256
#define NTHREADS 384
#define NW      12                   // MMA warps
#define NCHUNKS 16                   // 512 interleaved gate cols in chunks of 32
#define XPITCH  400                  // bytes per X row (200 bf16, 16B-aligned rows)
#define CPITCH  129

// SMEM byte offsets
#define SM_XH 0                      // X hi: 128 x 400
#define SM_XL 51200                  // X lo
#define SM_C  102400                 // c: 128 j x 129 n fp32 (66048B)
#define SM_F  168448                 // float region
#define SMEM_TOTAL 181504

// ---- static device scratch ----
// W in per-lane MMA B-fragment layout: [nc][kk][nh][lane] -> uint4
// fh.x/.y = b-frag regs for n-subtile q=0, fh.z/.w = q=1
__device__ uint4 g_WFH[NCHUNKS * 12 * 2 * 32];
__device__ uint4 g_WFL[NCHUNKS * 12 * 2 * 32];
__device__ uint32_t g_H[(size_t)N_NODES * DH];        // h packed: hi | lo<<16

// prep: build B-fragment tables. One thread per uint32 (two bf16 along k).
__global__ void prep_frag(const float* __restrict__ Wih, const float* __restrict__ Whh) {
    int idx = blockIdx.x * blockDim.x + threadIdx.x;   // 49152 entries
    if (idx >= NCHUNKS * 12 * 2 * 32 * 4) return;
    int r    = idx & 3;
    int lane = (idx >> 2) & 31;
    int nh   = (idx >> 7) & 1;
    int tmp  = idx >> 8;
    int kk   = tmp % 12;
    int nc   = tmp / 12;
    int q = r >> 1, rr = r & 1;
    // gate-interleaved W' row index np = j*4 + g
    int np = nc * 32 + nh * 16 + q * 8 + (lane >> 2);
    int k0 = kk * 16 + (lane & 3) * 2 + rr * 8;        // even, k0+1 in same half
    int col = (np & 3) * 128 + (np >> 2);              // g*128 + j
    float w0 = (k0 < 64) ? Wih[k0 * 512 + col] : Whh[(k0 - 64) * 512 + col];
    int k1 = k0 + 1;
    float w1 = (k1 < 64) ? Wih[k1 * 512 + col] : Whh[(k1 - 64) * 512 + col];
    __nv_bfloat16 h0 = __float2bfloat16(w0);
    __nv_bfloat16 h1 = __float2bfloat16(w1);
    __nv_bfloat16 l0 = __float2bfloat16(w0 - __bfloat162float(h0));
    __nv_bfloat16 l1 = __float2bfloat16(w1 - __bfloat162float(h1));
    ((uint32_t*)g_WFH)[idx] = (uint32_t)__bfloat16_as_ushort(h0) | ((uint32_t)__bfloat16_as_ushort(h1) << 16);
    ((uint32_t*)g_WFL)[idx] = (uint32_t)__bfloat16_as_ushort(l0) | ((uint32_t)__bfloat16_as_ushort(l1) << 16);
}

// ---- PTX helpers (portable ISA only) ----
__device__ __forceinline__ uint32_t smem_u32(const void* p) {
    uint32_t a;
    asm("{ .reg .u64 t; cvta.to.shared.u64 t, %1; cvt.u32.u64 %0, t; }" : "=r"(a) : "l"(p));
    return a;
}
__device__ __forceinline__ void ldsm4(uint32_t& r0, uint32_t& r1, uint32_t& r2, uint32_t& r3, uint32_t addr) {
    asm volatile("ldmatrix.sync.aligned.m8n8.x4.shared.b16 {%0,%1,%2,%3}, [%4];"
                 : "=r"(r0), "=r"(r1), "=r"(r2), "=r"(r3) : "r"(addr));
}
__device__ __forceinline__ void mma16816b(float* d, const uint32_t* a, uint32_t b0, uint32_t b1) {
    asm volatile("mma.sync.aligned.m16n8k16.row.col.f32.bf16.bf16.f32 "
                 "{%0,%1,%2,%3},{%4,%5,%6,%7},{%8,%9},{%0,%1,%2,%3};"
                 : "+f"(d[0]), "+f"(d[1]), "+f"(d[2]), "+f"(d[3])
                 : "r"(a[0]), "r"(a[1]), "r"(a[2]), "r"(a[3]), "r"(b0), "r"(b1));
}
__device__ __forceinline__ float tanh_apx(float x) {
    float y;
    asm("tanh.approx.f32 %0, %1;" : "=f"(y) : "f"(x));
    return y;
}
__device__ __forceinline__ float sigm(float x) { return fmaf(0.5f, tanh_apx(0.5f * x), 0.5f); }
__device__ __forceinline__ void bf16_split(float v, unsigned short& hi, unsigned short& lo) {
    __nv_bfloat16 h = __float2bfloat16(v);
    hi = __bfloat16_as_ushort(h);
    lo = __bfloat16_as_ushort(__float2bfloat16(v - __bfloat162float(h)));
}
__device__ __forceinline__ float unpackH(uint32_t w) {
    return __bfloat162float(__ushort_as_bfloat16((unsigned short)(w & 0xffff)))
         + __bfloat162float(__ushort_as_bfloat16((unsigned short)(w >> 16)));
}

__global__ __launch_bounds__(NTHREADS, 1)
void vlstm_mma(const float* __restrict__ nodes,
               const int* __restrict__ mask,
               const float* __restrict__ h0,
               const float* __restrict__ c0,
               const float* __restrict__ We,
               const float* __restrict__ be,
               const float* __restrict__ bih,
               const float* __restrict__ bhh,
               const float* __restrict__ Wout,
               const float* __restrict__ bout,
               float* __restrict__ out,
               float* __restrict__ hfin,
               float* __restrict__ cfin) {
    extern __shared__ char smem[];
    float* sc    = (float*)(smem + SM_C);   // [j][CPITCH]
    float* sBias = (float*)(smem + SM_F);   // 512
    float* sWe   = sBias + 512;             // 128
    float* sBe   = sWe + 128;               // 64
    float* sWout = sBe + 64;                // 640
    float* sBout = sWout + 640;             // 8
    float* sXY   = sBout + 8;               // 256
    float* sOutP = sXY + 256;               // 128 rows x 2 nh x 5
    int* sActive = (int*)(sOutP + 1280);    // 128
    int* sMask   = sActive + 128;           // 128
    int* sCnt    = sMask + 128;             // 2

    const int tid  = threadIdx.x;
    const int wid  = tid >> 5, lane = tid & 31;
    const int base = blockIdx.x * TILE_N;
    const uint32_t sbase = smem_u32(smem);

    // stage constants
    for (int i = tid; i < 512; i += NTHREADS) sBias[i] = bih[i] + bhh[i];
    for (int i = tid; i < 128; i += NTHREADS) sWe[i] = We[i];
    for (int i = tid; i < 64;  i += NTHREADS) sBe[i] = be[i];
    for (int i = tid; i < 640; i += NTHREADS) sWout[i] = Wout[i];
    if (tid < 5) sBout[tid] = bout[tid];

    // zero X buffers (padded-row hygiene)
    for (int i = tid; i < 12800; i += NTHREADS) {
        ((uint32_t*)(smem + SM_XH))[i] = 0;
        ((uint32_t*)(smem + SM_XL))[i] = 0;
    }
    // h0 -> g_H packed; c0 -> sc transposed
    for (int idx = tid; idx < TILE_N * DH; idx += NTHREADS) {
        int n = idx >> 7, j = idx & 127;
        unsigned short hb, lb;
        bf16_split(h0[(size_t)(base + n) * DH + j], hb, lb);
        g_H[(size_t)(base + n) * DH + j] = (uint32_t)hb | ((uint32_t)lb << 16);
        sc[j * CPITCH + n] = c0[(size_t)(base + n) * DH + j];
    }
    __syncthreads();

    // A-operand lane addressing (row within 16-row tile, 16B col offset)
    const uint32_t aoff = (uint32_t)((lane & 7) + ((lane >> 3) & 1) * 8) * XPITCH
                        + (uint32_t)(lane >> 4) * 16;
    const int p4 = lane & 3, odd = p4 & 1;

    for (int t = 0; t < T_STEPS; t++) {
        // ---- compaction (warp 0) ----
        if (tid < 32) {
            int cnt = 0;
            #pragma unroll
            for (int g2 = 0; g2 < 4; g2++) {
                int m = mask[(size_t)t * N_NODES + base + g2 * 32 + tid] != 0;
                sMask[g2 * 32 + tid] = m;
                unsigned b = __ballot_sync(0xffffffffu, m);
                if (m) sActive[cnt + __popc(b & ((1u << tid) - 1u))] = g2 * 32 + tid;
                cnt += __popc(b);
            }
            int pad = (cnt + 15) & ~15;
            __syncwarp();
            int dup = (cnt > 0) ? sActive[0] : 0;
            for (int p = cnt + tid; p < pad; p += 32) sActive[p] = dup;
            if (tid == 0) { sCnt[0] = cnt; sCnt[1] = pad; }
        }
        __syncthreads();
        const int cnt = sCnt[0];
        const int pad = sCnt[1];

        if (pad > 0) {
            // ---- stage xy + gather h (g_H -> X rows) ----
            if (tid < pad) {
                int n = base + sActive[tid];
                float2 xy = ((const float2*)nodes)[(size_t)t * N_NODES + n];
                sXY[2 * tid] = xy.x;
                sXY[2 * tid + 1] = xy.y;
            }
            for (int idx = tid; idx < pad * DH; idx += NTHREADS) {
                int a = idx >> 7, j = idx & 127;
                uint32_t w = g_H[(size_t)(base + sActive[a]) * DH + j];
                *(unsigned short*)(smem + SM_XH + a * XPITCH + 128 + 2 * j) = (unsigned short)(w & 0xffff);
                *(unsigned short*)(smem + SM_XL + a * XPITCH + 128 + 2 * j) = (unsigned short)(w >> 16);
            }
            __syncthreads();  // sXY ready for emb build below (also X-h rows progressing)

            // ---- emb rows (X cols 0..63) ----
            for (int idx = tid; idx < pad * 64; idx += NTHREADS) {
                int a = idx >> 6, k = idx & 63;
                float e = fmaxf(fmaf(sXY[2 * a], sWe[k],
                                fmaf(sXY[2 * a + 1], sWe[64 + k], sBe[k])), 0.0f);
                unsigned short hi, lo;
                bf16_split(e, hi, lo);
                *(unsigned short*)(smem + SM_XH + a * XPITCH + 2 * k) = hi;
                *(unsigned short*)(smem + SM_XL + a * XPITCH + 2 * k) = lo;
            }
            __syncthreads();  // full X visible to all MMA warps

            const int ntasks = (pad >> 4) * 2;   // (16-row tile) x (n-half); <= 16
            float oaccA[5] = {0.f, 0.f, 0.f, 0.f, 0.f};
            float oaccB[5] = {0.f, 0.f, 0.f, 0.f, 0.f};

            // ---- chunk loop: NO barriers inside ----
            for (int nc = 0; nc < NCHUNKS; nc++) {
                for (int task = wid; task < ntasks; task += NW) {
                    const int mt = task >> 1;
                    const int nh = task & 1;
                    float* oacc = (task < NW) ? oaccA : oaccB;
                    float acc[2][4];
                    #pragma unroll
                    for (int q = 0; q < 2; q++)
                        #pragma unroll
                        for (int z = 0; z < 4; z++) acc[q][z] = 0.0f;

                    const uint32_t xh = sbase + SM_XH + (uint32_t)mt * 16 * XPITCH + aoff;
                    const uint32_t xl = sbase + SM_XL + (uint32_t)mt * 16 * XPITCH + aoff;
                    const uint4* wfh = g_WFH + ((nc * 12) * 2 + nh) * 32 + lane;
                    const uint4* wfl = g_WFL + ((nc * 12) * 2 + nh) * 32 + lane;

                    #pragma unroll 4
                    for (int kk = 0; kk < 12; kk++) {
                        uint32_t kb = kk * 32;
                        uint4 fh = wfh[kk * 64];   // stride (2*32) uint4 per kk
                        uint4 fl = wfl[kk * 64];
                        uint32_t ah[4], al[4];
                        ldsm4(ah[0], ah[1], ah[2], ah[3], xh + kb);
                        ldsm4(al[0], al[1], al[2], al[3], xl + kb);
                        mma16816b(acc[0], ah, fh.x, fh.y);
                        mma16816b(acc[1], ah, fh.z, fh.w);
                        mma16816b(acc[0], al, fh.x, fh.y);
                        mma16816b(acc[1], al, fh.z, fh.w);
                        mma16816b(acc[0], ah, fl.x, fl.y);
                        mma16816b(acc[1], ah, fl.z, fl.w);
                    }

                    // ---- epilogue: gate exchange + cell update + fused out partials ----
                    #pragma unroll
                    for (int q = 0; q < 2; q++) {
                        float* d = acc[q];
                        float v0 = odd ? d[0] : d[2];
                        float v1 = odd ? d[1] : d[3];
                        float r0 = __shfl_xor_sync(0xffffffffu, v0, 1);
                        float r1 = __shfl_xor_sync(0xffffffffu, v1, 1);
                        float gi, gf, gg, go;
                        int row;
                        if (!odd) { gi = d[0]; gf = d[1]; gg = r0; go = r1; row = mt * 16 + (lane >> 2); }
                        else      { gi = r0;   gf = r1;   gg = d[2]; go = d[3]; row = mt * 16 + (lane >> 2) + 8; }
                        int j = nc * 8 + nh * 4 + q * 2 + (p4 >> 1);
                        if (row < cnt) {
                            int n = sActive[row];
                            float iv = sigm(gi + sBias[j]);
                            float fv = sigm(gf + sBias[128 + j]);
                            float gv = tanh_apx(gg + sBias[256 + j]);
                            float ov = sigm(go + sBias[384 + j]);
                            float cn = fmaf(fv, sc[j * CPITCH + n], iv * gv);
                            float hn = ov * tanh_apx(cn);
                            sc[j * CPITCH + n] = cn;
                            unsigned short hb, lb;
                            bf16_split(hn, hb, lb);
                            g_H[(size_t)(base + n) * DH + j] = (uint32_t)hb | ((uint32_t)lb << 16);
                            const float* w0 = sWout + j * 5;
                            oacc[0] = fmaf(hn, w0[0], oacc[0]);
                            oacc[1] = fmaf(hn, w0[1], oacc[1]);
                            oacc[2] = fmaf(hn, w0[2], oacc[2]);
                            oacc[3] = fmaf(hn, w0[3], oacc[3]);
                            oacc[4] = fmaf(hn, w0[4], oacc[4]);
                        }
                    }
                }
            }

            // ---- flush fused out partials: combine lane pairs (xor 2), store per (row, nh) ----
            #pragma unroll
            for (int slot = 0; slot < 2; slot++) {
                int task = wid + slot * NW;
                float* oa = slot ? oaccB : oaccA;
                if (task < ntasks) {
                    int mt = task >> 1, nh = task & 1;
                    float comb[5];
                    #pragma unroll
                    for (int z = 0; z < 5; z++)
                        comb[z] = oa[z] + __shfl_xor_sync(0xffffffffu, oa[z], 2);
                    int row = mt * 16 + (lane >> 2) + (lane & 1) * 8;
                    if ((lane & 3) < 2 && row < pad) {
                        float* s = sOutP + (row * 2 + nh) * 5;
                        s[0] = comb[0]; s[1] = comb[1]; s[2] = comb[2];
                        s[3] = comb[3]; s[4] = comb[4];
                    }
                }
            }
            __syncthreads();
        }

        // ---- write outputs ----
        if (tid < cnt) {
            int n = sActive[tid];
            float* pa = sOutP + tid * 10;
            float* op = out + ((size_t)t * N_NODES + base + n) * 5;
            op[0] = pa[0] + pa[5] + sBout[0];
            op[1] = pa[1] + pa[6] + sBout[1];
            op[2] = pa[2] + pa[7] + sBout[2];
            op[3] = pa[3] + pa[8] + sBout[3];
            op[4] = pa[4] + pa[9] + sBout[4];
        }
        if (tid < TILE_N && !sMask[tid]) {
            float* op = out + ((size_t)t * N_NODES + base + tid) * 5;
            op[0] = 0.f; op[1] = 0.f; op[2] = 0.f; op[3] = 0.f; op[4] = 0.f;
        }
        __syncthreads();
    }

    // ---- final h, c ----
    for (int idx = tid; idx < TILE_N * DH; idx += NTHREADS) {
        int n = idx >> 7, j = idx & 127;
        hfin[(size_t)(base + n) * DH + j] = unpackH(g_H[(size_t)(base + n) * DH + j]);
        cfin[(size_t)(base + n) * DH + j] = sc[j * CPITCH + n];
    }
}

extern "C" void kernel_launch(void* const* d_in, const int* in_sizes, int n_in,
                              void* d_out, int out_size) {
    const float* nodes = (const float*)d_in[0];
    const int* mask    = (const int*)d_in[1];     // bool -> int32
    const float* h0    = (const float*)d_in[2];
    const float* c0    = (const float*)d_in[3];
    const float* We    = (const float*)d_in[4];
    const float* be    = (const float*)d_in[5];
    const float* Wih   = (const float*)d_in[6];
    const float* bih   = (const float*)d_in[7];
    const float* Whh   = (const float*)d_in[8];
    const float* bhh   = (const float*)d_in[9];
    const float* Wout  = (const float*)d_in[10];
    const float* bout  = (const float*)d_in[11];

    float* out  = (float*)d_out;                            // [20, 32768, 5]
    float* hfin = out + (size_t)T_STEPS * N_NODES * 5;      // [32768, 128]
    float* cfin = hfin + (size_t)N_NODES * DH;              // [32768, 128]

    prep_frag<<<(NCHUNKS * 12 * 2 * 32 * 4 + 255) / 256, 256>>>(Wih, Whh);

    cudaFuncSetAttribute(vlstm_mma, cudaFuncAttributeMaxDynamicSharedMemorySize, SMEM_TOTAL);
    vlstm_mma<<<NBLOCKS, NTHREADS, SMEM_TOTAL>>>(
        nodes, mask, h0, c0, We, be, bih, bhh, Wout, bout, out, hfin, cfin);
}

// round 10
// speedup vs baseline: 1.0020x; 1.0020x over previous
#include <cuda_runtime.h>
#include <cuda_bf16.h>
#include <cstdint>

#define T_STEPS 20
#define N_NODES 32768
#define TILE_N  128
#define DH      128
#define NBLOCKS (N_NODES / TILE_N)   // 256
#define NTHREADS 256                 // 8 warps; warp w owns rows w*16..w*16+15
#define NCHUNKS 16                   // 512 interleaved gate cols in chunks of 32
#define XPITCH  400                  // bytes per X row (200 bf16; 100 words mod 32 = 4)
#define CPITCH  130                  // fp32 words per c row

// SMEM byte offsets
#define SM_XH 0                      // X hi: 128 x 400
#define SM_XL 51200                  // X lo: 128 x 400
#define SM_C  102400                 // c: [n][CPITCH] fp32 = 128*130*4 = 66560
#define SM_F  168960                 // float region: 512+128+64+640+8 = 1352 floats
#define SMEM_TOTAL (168960 + 5408)

// ---- static device scratch ----
// W in per-lane MMA B-fragment layout: flat idx = ((nc*12 + kk)*2 + nh)*32 + lane
__device__ uint4 g_WFH[NCHUNKS * 12 * 2 * 32];
__device__ uint4 g_WFL[NCHUNKS * 12 * 2 * 32];

// prep: build B-fragment tables. One thread per uint32 (two bf16 along k).
__global__ void prep_frag(const float* __restrict__ Wih, const float* __restrict__ Whh) {
    int idx = blockIdx.x * blockDim.x + threadIdx.x;
    if (idx >= NCHUNKS * 12 * 2 * 32 * 4) return;
    int r    = idx & 3;
    int lane = (idx >> 2) & 31;
    int nh   = (idx >> 7) & 1;
    int tmp  = idx >> 8;
    int kk   = tmp % 12;
    int nc   = tmp / 12;
    int q = r >> 1, rr = r & 1;
    int np = nc * 32 + nh * 16 + q * 8 + (lane >> 2);   // gate-interleaved row j*4+g
    int k0 = kk * 16 + (lane & 3) * 2 + rr * 8;
    int col = (np & 3) * 128 + (np >> 2);               // g*128 + j
    float w0 = (k0 < 64) ? Wih[k0 * 512 + col] : Whh[(k0 - 64) * 512 + col];
    int k1 = k0 + 1;
    float w1 = (k1 < 64) ? Wih[k1 * 512 + col] : Whh[(k1 - 64) * 512 + col];
    __nv_bfloat16 h0 = __float2bfloat16(w0);
    __nv_bfloat16 h1 = __float2bfloat16(w1);
    __nv_bfloat16 l0 = __float2bfloat16(w0 - __bfloat162float(h0));
    __nv_bfloat16 l1 = __float2bfloat16(w1 - __bfloat162float(h1));
    ((uint32_t*)g_WFH)[idx] = (uint32_t)__bfloat16_as_ushort(h0) | ((uint32_t)__bfloat16_as_ushort(h1) << 16);
    ((uint32_t*)g_WFL)[idx] = (uint32_t)__bfloat16_as_ushort(l0) | ((uint32_t)__bfloat16_as_ushort(l1) << 16);
}

// ---- PTX helpers (portable ISA only) ----
__device__ __forceinline__ uint32_t smem_u32(const void* p) {
    uint32_t a;
    asm("{ .reg .u64 t; cvta.to.shared.u64 t, %1; cvt.u32.u64 %0, t; }" : "=r"(a) : "l"(p));
    return a;
}
__device__ __forceinline__ void ldsm4(uint32_t& r0, uint32_t& r1, uint32_t& r2, uint32_t& r3, uint32_t addr) {
    asm volatile("ldmatrix.sync.aligned.m8n8.x4.shared.b16 {%0,%1,%2,%3}, [%4];"
                 : "=r"(r0), "=r"(r1), "=r"(r2), "=r"(r3) : "r"(addr));
}
__device__ __forceinline__ void mma16816b(float* d, const uint32_t* a, uint32_t b0, uint32_t b1) {
    asm volatile("mma.sync.aligned.m16n8k16.row.col.f32.bf16.bf16.f32 "
                 "{%0,%1,%2,%3},{%4,%5,%6,%7},{%8,%9},{%0,%1,%2,%3};"
                 : "+f"(d[0]), "+f"(d[1]), "+f"(d[2]), "+f"(d[3])
                 : "r"(a[0]), "r"(a[1]), "r"(a[2]), "r"(a[3]), "r"(b0), "r"(b1));
}
__device__ __forceinline__ float tanh_apx(float x) {
    float y;
    asm("tanh.approx.f32 %0, %1;" : "=f"(y) : "f"(x));
    return y;
}
__device__ __forceinline__ float sigm(float x) { return fmaf(0.5f, tanh_apx(0.5f * x), 0.5f); }
__device__ __forceinline__ void bf16_split(float v, unsigned short& hi, unsigned short& lo) {
    __nv_bfloat16 h = __float2bfloat16(v);
    hi = __bfloat16_as_ushort(h);
    lo = __bfloat16_as_ushort(__float2bfloat16(v - __bfloat162float(h)));
}

__global__ __launch_bounds__(NTHREADS, 1)
void vlstm_mma(const float* __restrict__ nodes,
               const int* __restrict__ mask,
               const float* __restrict__ h0,
               const float* __restrict__ c0,
               const float* __restrict__ We,
               const float* __restrict__ be,
               const float* __restrict__ bih,
               const float* __restrict__ bhh,
               const float* __restrict__ Wout,
               const float* __restrict__ bout,
               float* __restrict__ out,
               float* __restrict__ hfin,
               float* __restrict__ cfin) {
    extern __shared__ char smem[];
    float* sc    = (float*)(smem + SM_C);   // [n][CPITCH]
    float* sBias = (float*)(smem + SM_F);   // 512
    float* sWe   = sBias + 512;             // 128
    float* sBe   = sWe + 128;               // 64
    float* sWout = sBe + 64;                // 640
    float* sBout = sWout + 640;             // 8

    const int tid  = threadIdx.x;
    const int wid  = tid >> 5, lane = tid & 31;
    const int base = blockIdx.x * TILE_N;
    const uint32_t sbase = smem_u32(smem);

    // ---- block init ----
    for (int i = tid; i < 512; i += NTHREADS) sBias[i] = bih[i] + bhh[i];
    for (int i = tid; i < 128; i += NTHREADS) sWe[i] = We[i];
    for (int i = tid; i < 64;  i += NTHREADS) sBe[i] = be[i];
    for (int i = tid; i < 640; i += NTHREADS) sWout[i] = Wout[i];
    if (tid < 5) sBout[tid] = bout[tid];
    // h0 -> X h-cols (split); c0 -> sc
    for (int idx = tid; idx < TILE_N * DH; idx += NTHREADS) {
        int n = idx >> 7, j = idx & 127;
        unsigned short hb, lb;
        bf16_split(h0[(size_t)(base + n) * DH + j], hb, lb);
        *(unsigned short*)(smem + SM_XH + n * XPITCH + 128 + 2 * j) = hb;
        *(unsigned short*)(smem + SM_XL + n * XPITCH + 128 + 2 * j) = lb;
        sc[n * CPITCH + j] = c0[(size_t)(base + n) * DH + j];
    }
    __syncthreads();

    // ---- warp-private geometry ----
    const int mt = wid;                       // warp owns rows mt*16 .. mt*16+15
    const uint32_t aoff = (uint32_t)((lane & 7) + ((lane >> 3) & 1) * 8) * XPITCH
                        + (uint32_t)(lane >> 4) * 16;
    const uint32_t xhBase = sbase + SM_XH + (uint32_t)mt * 16 * XPITCH;
    const uint32_t xlBase = sbase + SM_XL + (uint32_t)mt * 16 * XPITCH;
    const int p4 = lane & 3, odd = p4 & 1;
    const int row = mt * 16 + (lane >> 2) + odd * 8;   // this thread's epilogue row
    const int node = base + row;
    // emb-build assignment: lane -> row mt*16 + (lane>>1), k-half (lane&1)
    const int erow = mt * 16 + (lane >> 1);
    const int ekb  = (lane & 1) * 32;

    for (int t = 0; t < T_STEPS; t++) {
        const int act = mask[(size_t)t * N_NODES + node];

        // ---- emb rebuild (warp-private rows) ----
        {
            float2 xy = ((const float2*)nodes)[(size_t)t * N_NODES + base + erow];
            #pragma unroll 8
            for (int i = 0; i < 32; i++) {
                int k = ekb + i;
                float e = fmaxf(fmaf(xy.x, sWe[k], fmaf(xy.y, sWe[64 + k], sBe[k])), 0.0f);
                unsigned short hb, lb;
                bf16_split(e, hb, lb);
                *(unsigned short*)(smem + SM_XH + erow * XPITCH + 2 * k) = hb;
                *(unsigned short*)(smem + SM_XL + erow * XPITCH + 2 * k) = lb;
            }
        }
        __syncwarp();   // cross-lane SMEM visibility (emb + last step's h writes)

        // ---- load A fragments once per step (register-resident X) ----
        uint32_t AH[12][4], AL[12][4];
        #pragma unroll
        for (int kk = 0; kk < 12; kk++) {
            ldsm4(AH[kk][0], AH[kk][1], AH[kk][2], AH[kk][3], xhBase + aoff + kk * 32);
            ldsm4(AL[kk][0], AL[kk][1], AL[kk][2], AL[kk][3], xlBase + aoff + kk * 32);
        }

        float oacc[5] = {0.f, 0.f, 0.f, 0.f, 0.f};

        // ---- chunk loop (rolled), MMAs from registers + streamed W frags ----
        for (int nc = 0; nc < NCHUNKS; nc++) {
            const uint4* WH = g_WFH + (size_t)(nc * 12) * 64 + lane;   // [kk*64 + nh*32]
            const uint4* WL = g_WFL + (size_t)(nc * 12) * 64 + lane;
            float a00[4] = {0,0,0,0}, a01[4] = {0,0,0,0};
            float a10[4] = {0,0,0,0}, a11[4] = {0,0,0,0};

            uint4 nh0 = WH[0], nh1 = WH[32], nl0 = WL[0], nl1 = WL[32];
            #pragma unroll
            for (int kk = 0; kk < 12; kk++) {
                uint4 ch0 = nh0, ch1 = nh1, cl0 = nl0, cl1 = nl1;
                if (kk < 11) {
                    nh0 = WH[(kk + 1) * 64];
                    nh1 = WH[(kk + 1) * 64 + 32];
                    nl0 = WL[(kk + 1) * 64];
                    nl1 = WL[(kk + 1) * 64 + 32];
                }
                mma16816b(a00, AH[kk], ch0.x, ch0.y);
                mma16816b(a01, AH[kk], ch0.z, ch0.w);
                mma16816b(a10, AH[kk], ch1.x, ch1.y);
                mma16816b(a11, AH[kk], ch1.z, ch1.w);
                mma16816b(a00, AL[kk], ch0.x, ch0.y);
                mma16816b(a01, AL[kk], ch0.z, ch0.w);
                mma16816b(a10, AL[kk], ch1.x, ch1.y);
                mma16816b(a11, AL[kk], ch1.z, ch1.w);
                mma16816b(a00, AH[kk], cl0.x, cl0.y);
                mma16816b(a01, AH[kk], cl0.z, cl0.w);
                mma16816b(a10, AH[kk], cl1.x, cl1.y);
                mma16816b(a11, AH[kk], cl1.z, cl1.w);
            }

            // ---- epilogue: gate exchange + masked cell update + h writeback ----
            float* accs[4] = {a00, a01, a10, a11};
            #pragma unroll
            for (int nh = 0; nh < 2; nh++) {
                #pragma unroll
                for (int q = 0; q < 2; q++) {
                    float* d = accs[nh * 2 + q];
                    float v0 = odd ? d[0] : d[2];
                    float v1 = odd ? d[1] : d[3];
                    float r0 = __shfl_xor_sync(0xffffffffu, v0, 1);
                    float r1 = __shfl_xor_sync(0xffffffffu, v1, 1);
                    float gi, gf, gg, go;
                    if (!odd) { gi = d[0]; gf = d[1]; gg = r0; go = r1; }
                    else      { gi = r0;   gf = r1;   gg = d[2]; go = d[3]; }
                    int j = nc * 8 + nh * 4 + q * 2 + (p4 >> 1);
                    if (act) {
                        float iv = sigm(gi + sBias[j]);
                        float fv = sigm(gf + sBias[128 + j]);
                        float gv = tanh_apx(gg + sBias[256 + j]);
                        float ov = sigm(go + sBias[384 + j]);
                        float cn = fmaf(fv, sc[row * CPITCH + j], iv * gv);
                        float hn = ov * tanh_apx(cn);
                        sc[row * CPITCH + j] = cn;
                        unsigned short hb, lb;
                        bf16_split(hn, hb, lb);
                        *(unsigned short*)(smem + SM_XH + row * XPITCH + 128 + 2 * j) = hb;
                        *(unsigned short*)(smem + SM_XL + row * XPITCH + 128 + 2 * j) = lb;
                        const float* w0 = sWout + j * 5;
                        oacc[0] = fmaf(hn, w0[0], oacc[0]);
                        oacc[1] = fmaf(hn, w0[1], oacc[1]);
                        oacc[2] = fmaf(hn, w0[2], oacc[2]);
                        oacc[3] = fmaf(hn, w0[3], oacc[3]);
                        oacc[4] = fmaf(hn, w0[4], oacc[4]);
                    }
                }
            }
        }

        // ---- combine j-halves (lane^2 partner has same row) and write out ----
        float comb[5];
        #pragma unroll
        for (int z = 0; z < 5; z++)
            comb[z] = oacc[z] + __shfl_xor_sync(0xffffffffu, oacc[z], 2);
        if (p4 < 2) {
            float* op = out + ((size_t)t * N_NODES + node) * 5;
            if (act) {
                op[0] = comb[0] + sBout[0];
                op[1] = comb[1] + sBout[1];
                op[2] = comb[2] + sBout[2];
                op[3] = comb[3] + sBout[3];
                op[4] = comb[4] + sBout[4];
            } else {
                op[0] = 0.f; op[1] = 0.f; op[2] = 0.f; op[3] = 0.f; op[4] = 0.f;
            }
        }
    }

    // ---- final h, c ----
    __syncthreads();
    for (int idx = tid; idx < TILE_N * DH; idx += NTHREADS) {
        int n = idx >> 7, j = idx & 127;
        float hv = __bfloat162float(__ushort_as_bfloat16(
                       *(unsigned short*)(smem + SM_XH + n * XPITCH + 128 + 2 * j)))
                 + __bfloat162float(__ushort_as_bfloat16(
                       *(unsigned short*)(smem + SM_XL + n * XPITCH + 128 + 2 * j)));
        hfin[(size_t)(base + n) * DH + j] = hv;
        cfin[(size_t)(base + n) * DH + j] = sc[n * CPITCH + j];
    }
}

extern "C" void kernel_launch(void* const* d_in, const int* in_sizes, int n_in,
                              void* d_out, int out_size) {
    const float* nodes = (const float*)d_in[0];
    const int* mask    = (const int*)d_in[1];     // bool -> int32
    const float* h0    = (const float*)d_in[2];
    const float* c0    = (const float*)d_in[3];
    const float* We    = (const float*)d_in[4];
    const float* be    = (const float*)d_in[5];
    const float* Wih   = (const float*)d_in[6];
    const float* bih   = (const float*)d_in[7];
    const float* Whh   = (const float*)d_in[8];
    const float* bhh   = (const float*)d_in[9];
    const float* Wout  = (const float*)d_in[10];
    const float* bout  = (const float*)d_in[11];

    float* out  = (float*)d_out;                            // [20, 32768, 5]
    float* hfin = out + (size_t)T_STEPS * N_NODES * 5;      // [32768, 128]
    float* cfin = hfin + (size_t)N_NODES * DH;              // [32768, 128]

    prep_frag<<<(NCHUNKS * 12 * 2 * 32 * 4 + 255) / 256, 256>>>(Wih, Whh);

    cudaFuncSetAttribute(vlstm_mma, cudaFuncAttributeMaxDynamicSharedMemorySize, SMEM_TOTAL);
    vlstm_mma<<<NBLOCKS, NTHREADS, SMEM_TOTAL>>>(
        nodes, mask, h0, c0, We, be, bih, bhh, Wout, bout, out, hfin, cfin);
}

// round 11
// speedup vs baseline: 1.0405x; 1.0384x over previous
#include <cuda_runtime.h>
#include <cuda_bf16.h>
#include <cstdint>

#define T_STEPS 20
#define N_NODES 32768
#define TILE_N  128
#define DH      128
#define NBLOCKS (N_NODES / TILE_N)   // 256
#define NTHREADS 256                 // 8 warps; warp w owns rows w*16..w*16+15
#define NCHUNKS 16                   // 512 interleaved gate cols in chunks of 32
#define XPITCH  400                  // bytes per X row (200 bf16)
#define CPITCH  130                  // fp32 words per c row
#define WCH     12288                // per-chunk hi (or lo) frag bytes: 12*2*32*16
#define WBUF    24576                // per-chunk buffer (hi+lo)

// SMEM byte offsets
#define SM_XH 0                      // X hi: 128 x 400
#define SM_XL 51200                  // X lo
#define SM_WB 102400                 // 2 x WBUF = 49152
#define SM_C  151552                 // c: [n][CPITCH] fp32 = 66560
#define SM_F  218112                 // float region: 1352 floats
#define SMEM_TOTAL 223520

// ---- static device scratch ----
// W in per-lane MMA B-fragment layout: flat idx = ((nc*12 + kk)*2 + nh)*32 + lane
__device__ uint4 g_WFH[NCHUNKS * 12 * 2 * 32];
__device__ uint4 g_WFL[NCHUNKS * 12 * 2 * 32];

__global__ void prep_frag(const float* __restrict__ Wih, const float* __restrict__ Whh) {
    int idx = blockIdx.x * blockDim.x + threadIdx.x;
    if (idx >= NCHUNKS * 12 * 2 * 32 * 4) return;
    int r    = idx & 3;
    int lane = (idx >> 2) & 31;
    int nh   = (idx >> 7) & 1;
    int tmp  = idx >> 8;
    int kk   = tmp % 12;
    int nc   = tmp / 12;
    int q = r >> 1, rr = r & 1;
    int np = nc * 32 + nh * 16 + q * 8 + (lane >> 2);   // gate-interleaved row j*4+g
    int k0 = kk * 16 + (lane & 3) * 2 + rr * 8;
    int col = (np & 3) * 128 + (np >> 2);               // g*128 + j
    float w0 = (k0 < 64) ? Wih[k0 * 512 + col] : Whh[(k0 - 64) * 512 + col];
    int k1 = k0 + 1;
    float w1 = (k1 < 64) ? Wih[k1 * 512 + col] : Whh[(k1 - 64) * 512 + col];
    __nv_bfloat16 h0 = __float2bfloat16(w0);
    __nv_bfloat16 h1 = __float2bfloat16(w1);
    __nv_bfloat16 l0 = __float2bfloat16(w0 - __bfloat162float(h0));
    __nv_bfloat16 l1 = __float2bfloat16(w1 - __bfloat162float(h1));
    ((uint32_t*)g_WFH)[idx] = (uint32_t)__bfloat16_as_ushort(h0) | ((uint32_t)__bfloat16_as_ushort(h1) << 16);
    ((uint32_t*)g_WFL)[idx] = (uint32_t)__bfloat16_as_ushort(l0) | ((uint32_t)__bfloat16_as_ushort(l1) << 16);
}

// ---- PTX helpers (portable ISA only) ----
__device__ __forceinline__ uint32_t smem_u32(const void* p) {
    uint32_t a;
    asm("{ .reg .u64 t; cvta.to.shared.u64 t, %1; cvt.u32.u64 %0, t; }" : "=r"(a) : "l"(p));
    return a;
}
__device__ __forceinline__ void ldsm4(uint32_t& r0, uint32_t& r1, uint32_t& r2, uint32_t& r3, uint32_t addr) {
    asm volatile("ldmatrix.sync.aligned.m8n8.x4.shared.b16 {%0,%1,%2,%3}, [%4];"
                 : "=r"(r0), "=r"(r1), "=r"(r2), "=r"(r3) : "r"(addr));
}
__device__ __forceinline__ void mma16816b(float* d, const uint32_t* a, uint32_t b0, uint32_t b1) {
    asm volatile("mma.sync.aligned.m16n8k16.row.col.f32.bf16.bf16.f32 "
                 "{%0,%1,%2,%3},{%4,%5,%6,%7},{%8,%9},{%0,%1,%2,%3};"
                 : "+f"(d[0]), "+f"(d[1]), "+f"(d[2]), "+f"(d[3])
                 : "r"(a[0]), "r"(a[1]), "r"(a[2]), "r"(a[3]), "r"(b0), "r"(b1));
}
__device__ __forceinline__ void cpasync16(uint32_t dst, const void* src) {
    asm volatile("cp.async.cg.shared.global [%0], [%1], 16;" :: "r"(dst), "l"(src) : "memory");
}
#define CP_COMMIT() asm volatile("cp.async.commit_group;" ::: "memory")
#define CP_WAIT0()  asm volatile("cp.async.wait_group 0;" ::: "memory")

__device__ __forceinline__ float tanh_apx(float x) {
    float y;
    asm("tanh.approx.f32 %0, %1;" : "=f"(y) : "f"(x));
    return y;
}
__device__ __forceinline__ float sigm(float x) { return fmaf(0.5f, tanh_apx(0.5f * x), 0.5f); }
__device__ __forceinline__ void bf16_split(float v, unsigned short& hi, unsigned short& lo) {
    __nv_bfloat16 h = __float2bfloat16(v);
    hi = __bfloat16_as_ushort(h);
    lo = __bfloat16_as_ushort(__float2bfloat16(v - __bfloat162float(h)));
}

__global__ __launch_bounds__(NTHREADS, 1)
void vlstm_mma(const float* __restrict__ nodes,
               const int* __restrict__ mask,
               const float* __restrict__ h0,
               const float* __restrict__ c0,
               const float* __restrict__ We,
               const float* __restrict__ be,
               const float* __restrict__ bih,
               const float* __restrict__ bhh,
               const float* __restrict__ Wout,
               const float* __restrict__ bout,
               float* __restrict__ out,
               float* __restrict__ hfin,
               float* __restrict__ cfin) {
    extern __shared__ char smem[];
    float* sc    = (float*)(smem + SM_C);   // [n][CPITCH]
    float* sBias = (float*)(smem + SM_F);   // 512
    float* sWe   = sBias + 512;             // 128
    float* sBe   = sWe + 128;               // 64
    float* sWout = sBe + 64;                // 640
    float* sBout = sWout + 640;             // 8

    const int tid  = threadIdx.x;
    const int wid  = tid >> 5, lane = tid & 31;
    const int base = blockIdx.x * TILE_N;
    const uint32_t sbase = smem_u32(smem);

    // ---- block init ----
    for (int i = tid; i < 512; i += NTHREADS) sBias[i] = bih[i] + bhh[i];
    for (int i = tid; i < 128; i += NTHREADS) sWe[i] = We[i];
    for (int i = tid; i < 64;  i += NTHREADS) sBe[i] = be[i];
    for (int i = tid; i < 640; i += NTHREADS) sWout[i] = Wout[i];
    if (tid < 5) sBout[tid] = bout[tid];
    for (int idx = tid; idx < TILE_N * DH; idx += NTHREADS) {
        int n = idx >> 7, j = idx & 127;
        unsigned short hb, lb;
        bf16_split(h0[(size_t)(base + n) * DH + j], hb, lb);
        *(unsigned short*)(smem + SM_XH + n * XPITCH + 128 + 2 * j) = hb;
        *(unsigned short*)(smem + SM_XL + n * XPITCH + 128 + 2 * j) = lb;
        sc[n * CPITCH + j] = c0[(size_t)(base + n) * DH + j];
    }
    __syncthreads();

    // ---- warp-private geometry ----
    const int mt = wid;
    const uint32_t aoff = (uint32_t)((lane & 7) + ((lane >> 3) & 1) * 8) * XPITCH
                        + (uint32_t)(lane >> 4) * 16;
    const uint32_t xhBase = sbase + SM_XH + (uint32_t)mt * 16 * XPITCH;
    const uint32_t xlBase = sbase + SM_XL + (uint32_t)mt * 16 * XPITCH;
    const int p4 = lane & 3, odd = p4 & 1;
    const int row = mt * 16 + (lane >> 2) + odd * 8;
    const int node = base + row;
    const int erow = mt * 16 + (lane >> 1);
    const int ekb  = (lane & 1) * 32;

    for (int t = 0; t < T_STEPS; t++) {
        const int act = mask[(size_t)t * N_NODES + node];

        // ---- emb rebuild (warp-private rows) ----
        {
            float2 xy = ((const float2*)nodes)[(size_t)t * N_NODES + base + erow];
            #pragma unroll 8
            for (int i = 0; i < 32; i++) {
                int k = ekb + i;
                float e = fmaxf(fmaf(xy.x, sWe[k], fmaf(xy.y, sWe[64 + k], sBe[k])), 0.0f);
                unsigned short hb, lb;
                bf16_split(e, hb, lb);
                *(unsigned short*)(smem + SM_XH + erow * XPITCH + 2 * k) = hb;
                *(unsigned short*)(smem + SM_XL + erow * XPITCH + 2 * k) = lb;
            }
        }
        __syncwarp();

        // ---- prefetch chunk 0 W frags into SMEM buf 0 ----
        {
            uint32_t dst = sbase + SM_WB;
            const char* srcH = (const char*)g_WFH;
            const char* srcL = (const char*)g_WFL;
            #pragma unroll
            for (int i = 0; i < 3; i++) {
                int o = tid * 16 + i * 4096;
                cpasync16(dst + o, srcH + o);
                cpasync16(dst + WCH + o, srcL + o);
            }
            CP_COMMIT();
        }

        // ---- load A fragments once per step (register-resident X) ----
        uint32_t AH[12][4], AL[12][4];
        #pragma unroll
        for (int kk = 0; kk < 12; kk++) {
            ldsm4(AH[kk][0], AH[kk][1], AH[kk][2], AH[kk][3], xhBase + aoff + kk * 32);
            ldsm4(AL[kk][0], AL[kk][1], AL[kk][2], AL[kk][3], xlBase + aoff + kk * 32);
        }

        float oacc[5] = {0.f, 0.f, 0.f, 0.f, 0.f};

        // ---- chunk loop: SMEM W double-buffer, one sync per chunk ----
        for (int nc = 0; nc < NCHUNKS; nc++) {
            const int buf = nc & 1;
            CP_WAIT0();
            __syncthreads();   // W[buf] visible to all; prior reads of buf^1 done
            if (nc + 1 < NCHUNKS) {
                uint32_t dst = sbase + SM_WB + (buf ^ 1) * WBUF;
                const char* srcH = (const char*)g_WFH + (nc + 1) * WCH;
                const char* srcL = (const char*)g_WFL + (nc + 1) * WCH;
                #pragma unroll
                for (int i = 0; i < 3; i++) {
                    int o = tid * 16 + i * 4096;
                    cpasync16(dst + o, srcH + o);
                    cpasync16(dst + WCH + o, srcL + o);
                }
                CP_COMMIT();
            }

            const char* wch = smem + SM_WB + buf * WBUF;   // hi; lo at +WCH
            float a00[4] = {0,0,0,0}, a01[4] = {0,0,0,0};
            float a10[4] = {0,0,0,0}, a11[4] = {0,0,0,0};

            // kk-level register prefetch from SMEM (29-cyc LDS, dist-1 cover)
            uint4 nh0 = *(const uint4*)(wch + (lane)*16);
            uint4 nh1 = *(const uint4*)(wch + (32 + lane)*16);
            uint4 nl0 = *(const uint4*)(wch + WCH + (lane)*16);
            uint4 nl1 = *(const uint4*)(wch + WCH + (32 + lane)*16);
            #pragma unroll
            for (int kk = 0; kk < 12; kk++) {
                uint4 ch0 = nh0, ch1 = nh1, cl0 = nl0, cl1 = nl1;
                if (kk < 11) {
                    int o = (kk + 1) * 64 + lane;
                    nh0 = *(const uint4*)(wch + o * 16);
                    nh1 = *(const uint4*)(wch + (o + 32) * 16);
                    nl0 = *(const uint4*)(wch + WCH + o * 16);
                    nl1 = *(const uint4*)(wch + WCH + (o + 32) * 16);
                }
                mma16816b(a00, AH[kk], ch0.x, ch0.y);
                mma16816b(a01, AH[kk], ch0.z, ch0.w);
                mma16816b(a10, AH[kk], ch1.x, ch1.y);
                mma16816b(a11, AH[kk], ch1.z, ch1.w);
                mma16816b(a00, AL[kk], ch0.x, ch0.y);
                mma16816b(a01, AL[kk], ch0.z, ch0.w);
                mma16816b(a10, AL[kk], ch1.x, ch1.y);
                mma16816b(a11, AL[kk], ch1.z, ch1.w);
                mma16816b(a00, AH[kk], cl0.x, cl0.y);
                mma16816b(a01, AH[kk], cl0.z, cl0.w);
                mma16816b(a10, AH[kk], cl1.x, cl1.y);
                mma16816b(a11, AH[kk], cl1.z, cl1.w);
            }

            // ---- epilogue: gate exchange + masked cell update + h writeback ----
            float* accs[4] = {a00, a01, a10, a11};
            #pragma unroll
            for (int nh = 0; nh < 2; nh++) {
                #pragma unroll
                for (int q = 0; q < 2; q++) {
                    float* d = accs[nh * 2 + q];
                    float v0 = odd ? d[0] : d[2];
                    float v1 = odd ? d[1] : d[3];
                    float r0 = __shfl_xor_sync(0xffffffffu, v0, 1);
                    float r1 = __shfl_xor_sync(0xffffffffu, v1, 1);
                    float gi, gf, gg, go;
                    if (!odd) { gi = d[0]; gf = d[1]; gg = r0; go = r1; }
                    else      { gi = r0;   gf = r1;   gg = d[2]; go = d[3]; }
                    int j = nc * 8 + nh * 4 + q * 2 + (p4 >> 1);
                    if (act) {
                        float iv = sigm(gi + sBias[j]);
                        float fv = sigm(gf + sBias[128 + j]);
                        float gv = tanh_apx(gg + sBias[256 + j]);
                        float ov = sigm(go + sBias[384 + j]);
                        float cn = fmaf(fv, sc[row * CPITCH + j], iv * gv);
                        float hn = ov * tanh_apx(cn);
                        sc[row * CPITCH + j] = cn;
                        unsigned short hb, lb;
                        bf16_split(hn, hb, lb);
                        *(unsigned short*)(smem + SM_XH + row * XPITCH + 128 + 2 * j) = hb;
                        *(unsigned short*)(smem + SM_XL + row * XPITCH + 128 + 2 * j) = lb;
                        const float* w0 = sWout + j * 5;
                        oacc[0] = fmaf(hn, w0[0], oacc[0]);
                        oacc[1] = fmaf(hn, w0[1], oacc[1]);
                        oacc[2] = fmaf(hn, w0[2], oacc[2]);
                        oacc[3] = fmaf(hn, w0[3], oacc[3]);
                        oacc[4] = fmaf(hn, w0[4], oacc[4]);
                    }
                }
            }
        }

        // ---- combine j-halves (lane^2 partner has same row) and write out ----
        float comb[5];
        #pragma unroll
        for (int z = 0; z < 5; z++)
            comb[z] = oacc[z] + __shfl_xor_sync(0xffffffffu, oacc[z], 2);
        if (p4 < 2) {
            float* op = out + ((size_t)t * N_NODES + node) * 5;
            if (act) {
                op[0] = comb[0] + sBout[0];
                op[1] = comb[1] + sBout[1];
                op[2] = comb[2] + sBout[2];
                op[3] = comb[3] + sBout[3];
                op[4] = comb[4] + sBout[4];
            } else {
                op[0] = 0.f; op[1] = 0.f; op[2] = 0.f; op[3] = 0.f; op[4] = 0.f;
            }
        }
    }

    // ---- final h, c ----
    __syncthreads();
    for (int idx = tid; idx < TILE_N * DH; idx += NTHREADS) {
        int n = idx >> 7, j = idx & 127;
        float hv = __bfloat162float(__ushort_as_bfloat16(
                       *(unsigned short*)(smem + SM_XH + n * XPITCH + 128 + 2 * j)))
                 + __bfloat162float(__ushort_as_bfloat16(
                       *(unsigned short*)(smem + SM_XL + n * XPITCH + 128 + 2 * j)));
        hfin[(size_t)(base + n) * DH + j] = hv;
        cfin[(size_t)(base + n) * DH + j] = sc[n * CPITCH + j];
    }
}

extern "C" void kernel_launch(void* const* d_in, const int* in_sizes, int n_in,
                              void* d_out, int out_size) {
    const float* nodes = (const float*)d_in[0];
    const int* mask    = (const int*)d_in[1];     // bool -> int32
    const float* h0    = (const float*)d_in[2];
    const float* c0    = (const float*)d_in[3];
    const float* We    = (const float*)d_in[4];
    const float* be    = (const float*)d_in[5];
    const float* Wih   = (const float*)d_in[6];
    const float* bih   = (const float*)d_in[7];
    const float* Whh   = (const float*)d_in[8];
    const float* bhh   = (const float*)d_in[9];
    const float* Wout  = (const float*)d_in[10];
    const float* bout  = (const float*)d_in[11];

    float* out  = (float*)d_out;                            // [20, 32768, 5]
    float* hfin = out + (size_t)T_STEPS * N_NODES * 5;      // [32768, 128]
    float* cfin = hfin + (size_t)N_NODES * DH;              // [32768, 128]

    prep_frag<<<(NCHUNKS * 12 * 2 * 32 * 4 + 255) / 256, 256>>>(Wih, Whh);

    cudaFuncSetAttribute(vlstm_mma, cudaFuncAttributeMaxDynamicSharedMemorySize, SMEM_TOTAL);
    vlstm_mma<<<NBLOCKS, NTHREADS, SMEM_TOTAL>>>(
        nodes, mask, h0, c0, We, be, bih, bhh, Wout, bout, out, hfin, cfin);
}

// round 12
// speedup vs baseline: 1.1752x; 1.1294x over previous
#include <cuda_runtime.h>
#include <cuda_bf16.h>
#include <cstdint>

#define T_STEPS 20
#define N_NODES 32768
#define TILE_N  128
#define DH      128
#define NBLOCKS (N_NODES / TILE_N)   // 256
#define NTHREADS 256                 // 8 warps; warp w owns rows w*16..w*16+15
#define NCHUNKS 16
#define XPITCH  400                  // bytes per X row (200 bf16)
#define CPITCH  130
#define WCH     12288                // per-chunk hi (or lo) frag bytes
#define WBUF    24576

// SMEM byte offsets
#define SM_XH 0
#define SM_XL 51200
#define SM_WB 102400                 // 2 x WBUF
#define SM_C  151552                 // 66560
#define SM_F  218112
#define SMEM_TOTAL 223520

__device__ uint4 g_WFH[NCHUNKS * 12 * 2 * 32];
__device__ uint4 g_WFL[NCHUNKS * 12 * 2 * 32];

__global__ void prep_frag(const float* __restrict__ Wih, const float* __restrict__ Whh) {
    int idx = blockIdx.x * blockDim.x + threadIdx.x;
    if (idx >= NCHUNKS * 12 * 2 * 32 * 4) return;
    int r    = idx & 3;
    int lane = (idx >> 2) & 31;
    int nh   = (idx >> 7) & 1;
    int tmp  = idx >> 8;
    int kk   = tmp % 12;
    int nc   = tmp / 12;
    int q = r >> 1, rr = r & 1;
    int np = nc * 32 + nh * 16 + q * 8 + (lane >> 2);
    int k0 = kk * 16 + (lane & 3) * 2 + rr * 8;
    int col = (np & 3) * 128 + (np >> 2);
    float w0 = (k0 < 64) ? Wih[k0 * 512 + col] : Whh[(k0 - 64) * 512 + col];
    int k1 = k0 + 1;
    float w1 = (k1 < 64) ? Wih[k1 * 512 + col] : Whh[(k1 - 64) * 512 + col];
    __nv_bfloat16 h0 = __float2bfloat16(w0);
    __nv_bfloat16 h1 = __float2bfloat16(w1);
    __nv_bfloat16 l0 = __float2bfloat16(w0 - __bfloat162float(h0));
    __nv_bfloat16 l1 = __float2bfloat16(w1 - __bfloat162float(h1));
    ((uint32_t*)g_WFH)[idx] = (uint32_t)__bfloat16_as_ushort(h0) | ((uint32_t)__bfloat16_as_ushort(h1) << 16);
    ((uint32_t*)g_WFL)[idx] = (uint32_t)__bfloat16_as_ushort(l0) | ((uint32_t)__bfloat16_as_ushort(l1) << 16);
}

__device__ __forceinline__ uint32_t smem_u32(const void* p) {
    uint32_t a;
    asm("{ .reg .u64 t; cvta.to.shared.u64 t, %1; cvt.u32.u64 %0, t; }" : "=r"(a) : "l"(p));
    return a;
}
__device__ __forceinline__ void ldsm4(uint32_t& r0, uint32_t& r1, uint32_t& r2, uint32_t& r3, uint32_t addr) {
    asm volatile("ldmatrix.sync.aligned.m8n8.x4.shared.b16 {%0,%1,%2,%3}, [%4];"
                 : "=r"(r0), "=r"(r1), "=r"(r2), "=r"(r3) : "r"(addr));
}
__device__ __forceinline__ void mma16816b(float* d, const uint32_t* a, uint32_t b0, uint32_t b1) {
    asm volatile("mma.sync.aligned.m16n8k16.row.col.f32.bf16.bf16.f32 "
                 "{%0,%1,%2,%3},{%4,%5,%6,%7},{%8,%9},{%0,%1,%2,%3};"
                 : "+f"(d[0]), "+f"(d[1]), "+f"(d[2]), "+f"(d[3])
                 : "r"(a[0]), "r"(a[1]), "r"(a[2]), "r"(a[3]), "r"(b0), "r"(b1));
}
__device__ __forceinline__ void cpasync16(uint32_t dst, const void* src) {
    asm volatile("cp.async.cg.shared.global [%0], [%1], 16;" :: "r"(dst), "l"(src) : "memory");
}
#define CP_COMMIT() asm volatile("cp.async.commit_group;" ::: "memory")
#define CP_WAIT0()  asm volatile("cp.async.wait_group 0;" ::: "memory")

__device__ __forceinline__ float tanh_apx(float x) {
    float y;
    asm("tanh.approx.f32 %0, %1;" : "=f"(y) : "f"(x));
    return y;
}
__device__ __forceinline__ float sigm(float x) { return fmaf(0.5f, tanh_apx(0.5f * x), 0.5f); }
__device__ __forceinline__ void bf16_split(float v, unsigned short& hi, unsigned short& lo) {
    __nv_bfloat16 h = __float2bfloat16(v);
    hi = __bfloat16_as_ushort(h);
    lo = __bfloat16_as_ushort(__float2bfloat16(v - __bfloat162float(h)));
}

__global__ __launch_bounds__(NTHREADS, 1)
void vlstm_mma(const float* __restrict__ nodes,
               const int* __restrict__ mask,
               const float* __restrict__ h0,
               const float* __restrict__ c0,
               const float* __restrict__ We,
               const float* __restrict__ be,
               const float* __restrict__ bih,
               const float* __restrict__ bhh,
               const float* __restrict__ Wout,
               const float* __restrict__ bout,
               float* __restrict__ out,
               float* __restrict__ hfin,
               float* __restrict__ cfin) {
    extern __shared__ char smem[];
    float* sc    = (float*)(smem + SM_C);
    float* sBias = (float*)(smem + SM_F);   // 512
    float* sWe   = sBias + 512;
    float* sBe   = sWe + 128;
    float* sWout = sBe + 64;
    float* sBout = sWout + 640;

    const int tid  = threadIdx.x;
    const int wid  = tid >> 5, lane = tid & 31;
    const int base = blockIdx.x * TILE_N;
    const uint32_t sbase = smem_u32(smem);

    for (int i = tid; i < 512; i += NTHREADS) sBias[i] = bih[i] + bhh[i];
    for (int i = tid; i < 128; i += NTHREADS) sWe[i] = We[i];
    for (int i = tid; i < 64;  i += NTHREADS) sBe[i] = be[i];
    for (int i = tid; i < 640; i += NTHREADS) sWout[i] = Wout[i];
    if (tid < 5) sBout[tid] = bout[tid];
    for (int idx = tid; idx < TILE_N * DH; idx += NTHREADS) {
        int n = idx >> 7, j = idx & 127;
        unsigned short hb, lb;
        bf16_split(h0[(size_t)(base + n) * DH + j], hb, lb);
        *(unsigned short*)(smem + SM_XH + n * XPITCH + 128 + 2 * j) = hb;
        *(unsigned short*)(smem + SM_XL + n * XPITCH + 128 + 2 * j) = lb;
        sc[n * CPITCH + j] = c0[(size_t)(base + n) * DH + j];
    }
    __syncthreads();

    const int mt = wid;
    const uint32_t aoff = (uint32_t)((lane & 7) + ((lane >> 3) & 1) * 8) * XPITCH
                        + (uint32_t)(lane >> 4) * 16;
    const uint32_t xhBase = sbase + SM_XH + (uint32_t)mt * 16 * XPITCH;
    const uint32_t xlBase = sbase + SM_XL + (uint32_t)mt * 16 * XPITCH;
    const int p4 = lane & 3, odd = p4 & 1;
    const int row = mt * 16 + (lane >> 2) + odd * 8;
    const int node = base + row;
    const int erow = mt * 16 + (lane >> 1);
    const int ekb  = (lane & 1) * 32;

    // Branch-free(ish) epilogue for one chunk from saved accumulators.
    // acc layout: acc[(nh*2+q)*4 + z]
    #define EPILOGUE(ACC, NCE)                                                       \
    {                                                                                \
        _Pragma("unroll")                                                            \
        for (int nh = 0; nh < 2; nh++) {                                             \
            _Pragma("unroll")                                                        \
            for (int q = 0; q < 2; q++) {                                            \
                float* d = (ACC) + (nh * 2 + q) * 4;                                 \
                float v0 = odd ? d[0] : d[2];                                        \
                float v1 = odd ? d[1] : d[3];                                        \
                float r0 = __shfl_xor_sync(0xffffffffu, v0, 1);                      \
                float r1 = __shfl_xor_sync(0xffffffffu, v1, 1);                      \
                float gi, gf, gg, go;                                                \
                if (!odd) { gi = d[0]; gf = d[1]; gg = r0; go = r1; }                 \
                else      { gi = r0;   gf = r1;   gg = d[2]; go = d[3]; }             \
                int j = (NCE) * 8 + nh * 4 + q * 2 + (p4 >> 1);                      \
                float cold = sc[row * CPITCH + j];                                   \
                float iv = sigm(gi + sBias[j]);                                      \
                float fv = sigm(gf + sBias[128 + j]);                                \
                float gv = tanh_apx(gg + sBias[256 + j]);                            \
                float ov = sigm(go + sBias[384 + j]);                                \
                float cn = fmaf(fv, cold, iv * gv);                                  \
                float hn = ov * tanh_apx(cn);                                        \
                sc[row * CPITCH + j] = act ? cn : cold;                              \
                float hg = act ? hn : 0.0f;                                          \
                if (act) {                                                           \
                    unsigned short hb, lb;                                           \
                    bf16_split(hn, hb, lb);                                          \
                    *(unsigned short*)(smem + SM_XH + row * XPITCH + 128 + 2 * j) = hb; \
                    *(unsigned short*)(smem + SM_XL + row * XPITCH + 128 + 2 * j) = lb; \
                }                                                                    \
                const float* w0 = sWout + j * 5;                                     \
                oacc[0] = fmaf(hg, w0[0], oacc[0]);                                  \
                oacc[1] = fmaf(hg, w0[1], oacc[1]);                                  \
                oacc[2] = fmaf(hg, w0[2], oacc[2]);                                  \
                oacc[3] = fmaf(hg, w0[3], oacc[3]);                                  \
                oacc[4] = fmaf(hg, w0[4], oacc[4]);                                  \
            }                                                                        \
        }                                                                            \
    }

    // MMA block for one chunk into ACC from W buffer BUF
    #define MMA_CHUNK(ACC, BUF)                                                      \
    {                                                                                \
        const char* wch = smem + SM_WB + (BUF) * WBUF;                               \
        _Pragma("unroll")                                                            \
        for (int z = 0; z < 16; z++) (ACC)[z] = 0.0f;                                \
        uint4 nh0 = *(const uint4*)(wch + (lane) * 16);                              \
        uint4 nh1 = *(const uint4*)(wch + (32 + lane) * 16);                         \
        uint4 nl0 = *(const uint4*)(wch + WCH + (lane) * 16);                        \
        uint4 nl1 = *(const uint4*)(wch + WCH + (32 + lane) * 16);                   \
        _Pragma("unroll")                                                            \
        for (int kk = 0; kk < 12; kk++) {                                            \
            uint4 ch0 = nh0, ch1 = nh1, cl0 = nl0, cl1 = nl1;                        \
            if (kk < 11) {                                                           \
                int o = (kk + 1) * 64 + lane;                                        \
                nh0 = *(const uint4*)(wch + o * 16);                                 \
                nh1 = *(const uint4*)(wch + (o + 32) * 16);                          \
                nl0 = *(const uint4*)(wch + WCH + o * 16);                           \
                nl1 = *(const uint4*)(wch + WCH + (o + 32) * 16);                    \
            }                                                                        \
            mma16816b((ACC) + 0,  AH[kk], ch0.x, ch0.y);                             \
            mma16816b((ACC) + 4,  AH[kk], ch0.z, ch0.w);                             \
            mma16816b((ACC) + 8,  AH[kk], ch1.x, ch1.y);                             \
            mma16816b((ACC) + 12, AH[kk], ch1.z, ch1.w);                             \
            mma16816b((ACC) + 0,  AL[kk], ch0.x, ch0.y);                             \
            mma16816b((ACC) + 4,  AL[kk], ch0.z, ch0.w);                             \
            mma16816b((ACC) + 8,  AL[kk], ch1.x, ch1.y);                             \
            mma16816b((ACC) + 12, AL[kk], ch1.z, ch1.w);                             \
            mma16816b((ACC) + 0,  AH[kk], cl0.x, cl0.y);                             \
            mma16816b((ACC) + 4,  AH[kk], cl0.z, cl0.w);                             \
            mma16816b((ACC) + 8,  AH[kk], cl1.x, cl1.y);                             \
            mma16816b((ACC) + 12, AH[kk], cl1.z, cl1.w);                             \
        }                                                                            \
    }

    #define PREFETCH_W(NC)                                                           \
    {                                                                                \
        uint32_t dst = sbase + SM_WB + ((NC) & 1) * WBUF;                            \
        const char* srcH = (const char*)g_WFH + (NC) * WCH;                          \
        const char* srcL = (const char*)g_WFL + (NC) * WCH;                          \
        _Pragma("unroll")                                                            \
        for (int i = 0; i < 3; i++) {                                                \
            int o = tid * 16 + i * 4096;                                             \
            cpasync16(dst + o, srcH + o);                                            \
            cpasync16(dst + WCH + o, srcL + o);                                      \
        }                                                                            \
        CP_COMMIT();                                                                 \
    }

    for (int t = 0; t < T_STEPS; t++) {
        const int act = mask[(size_t)t * N_NODES + node];

        // emb rebuild (warp-private rows), packed 32-bit stores
        {
            float2 xy = ((const float2*)nodes)[(size_t)t * N_NODES + base + erow];
            #pragma unroll 4
            for (int i = 0; i < 16; i++) {
                int k = ekb + 2 * i;
                float e0 = fmaxf(fmaf(xy.x, sWe[k], fmaf(xy.y, sWe[64 + k], sBe[k])), 0.0f);
                float e1 = fmaxf(fmaf(xy.x, sWe[k + 1], fmaf(xy.y, sWe[64 + k + 1], sBe[k + 1])), 0.0f);
                unsigned short h0b, l0b, h1b, l1b;
                bf16_split(e0, h0b, l0b);
                bf16_split(e1, h1b, l1b);
                *(uint32_t*)(smem + SM_XH + erow * XPITCH + 2 * k) = (uint32_t)h0b | ((uint32_t)h1b << 16);
                *(uint32_t*)(smem + SM_XL + erow * XPITCH + 2 * k) = (uint32_t)l0b | ((uint32_t)l1b << 16);
            }
        }
        __syncwarp();

        PREFETCH_W(0)

        // load A fragments once per step
        uint32_t AH[12][4], AL[12][4];
        #pragma unroll
        for (int kk = 0; kk < 12; kk++) {
            ldsm4(AH[kk][0], AH[kk][1], AH[kk][2], AH[kk][3], xhBase + aoff + kk * 32);
            ldsm4(AL[kk][0], AL[kk][1], AL[kk][2], AL[kk][3], xlBase + aoff + kk * 32);
        }

        float oacc[5] = {0.f, 0.f, 0.f, 0.f, 0.f};
        float accA[16], accB[16];

        // pipelined chunk loop, unrolled x2 for static acc parity
        for (int nc2 = 0; nc2 < NCHUNKS; nc2 += 2) {
            // even chunk -> accA; epilogue of previous odd chunk (accB)
            CP_WAIT0();
            __syncthreads();
            if (nc2 + 1 < NCHUNKS) PREFETCH_W(nc2 + 1)
            MMA_CHUNK(accA, 0)
            if (nc2 > 0) EPILOGUE(accB, nc2 - 1)

            // odd chunk -> accB; epilogue of even chunk (accA)
            CP_WAIT0();
            __syncthreads();
            if (nc2 + 2 < NCHUNKS) PREFETCH_W(nc2 + 2)
            MMA_CHUNK(accB, 1)
            EPILOGUE(accA, nc2)
        }
        EPILOGUE(accB, NCHUNKS - 1)

        // combine j-halves and write out
        float comb[5];
        #pragma unroll
        for (int z = 0; z < 5; z++)
            comb[z] = oacc[z] + __shfl_xor_sync(0xffffffffu, oacc[z], 2);
        if (p4 < 2) {
            float* op = out + ((size_t)t * N_NODES + node) * 5;
            if (act) {
                op[0] = comb[0] + sBout[0];
                op[1] = comb[1] + sBout[1];
                op[2] = comb[2] + sBout[2];
                op[3] = comb[3] + sBout[3];
                op[4] = comb[4] + sBout[4];
            } else {
                op[0] = 0.f; op[1] = 0.f; op[2] = 0.f; op[3] = 0.f; op[4] = 0.f;
            }
        }
    }

    __syncthreads();
    for (int idx = tid; idx < TILE_N * DH; idx += NTHREADS) {
        int n = idx >> 7, j = idx & 127;
        float hv = __bfloat162float(__ushort_as_bfloat16(
                       *(unsigned short*)(smem + SM_XH + n * XPITCH + 128 + 2 * j)))
                 + __bfloat162float(__ushort_as_bfloat16(
                       *(unsigned short*)(smem + SM_XL + n * XPITCH + 128 + 2 * j)));
        hfin[(size_t)(base + n) * DH + j] = hv;
        cfin[(size_t)(base + n) * DH + j] = sc[n * CPITCH + j];
    }
}

extern "C" void kernel_launch(void* const* d_in, const int* in_sizes, int n_in,
                              void* d_out, int out_size) {
    const float* nodes = (const float*)d_in[0];
    const int* mask    = (const int*)d_in[1];
    const float* h0    = (const float*)d_in[2];
    const float* c0    = (const float*)d_in[3];
    const float* We    = (const float*)d_in[4];
    const float* be    = (const float*)d_in[5];
    const float* Wih   = (const float*)d_in[6];
    const float* bih   = (const float*)d_in[7];
    const float* Whh   = (const float*)d_in[8];
    const float* bhh   = (const float*)d_in[9];
    const float* Wout  = (const float*)d_in[10];
    const float* bout  = (const float*)d_in[11];

    float* out  = (float*)d_out;
    float* hfin = out + (size_t)T_STEPS * N_NODES * 5;
    float* cfin = hfin + (size_t)N_NODES * DH;

    prep_frag<<<(NCHUNKS * 12 * 2 * 32 * 4 + 255) / 256, 256>>>(Wih, Whh);

    cudaFuncSetAttribute(vlstm_mma, cudaFuncAttributeMaxDynamicSharedMemorySize, SMEM_TOTAL);
    vlstm_mma<<<NBLOCKS, NTHREADS, SMEM_TOTAL>>>(
        nodes, mask, h0, c0, We, be, bih, bhh, Wout, bout, out, hfin, cfin);
}

// round 13
// speedup vs baseline: 1.2568x; 1.0695x over previous
#include <cuda_runtime.h>
#include <cuda_bf16.h>
#include <cstdint>

#define T_STEPS 20
#define N_NODES 32768
#define TILE_N  64
#define DH      128
#define NBLOCKS (N_NODES / TILE_N)   // 512
#define NTHREADS 128                 // 4 warps; warp w owns rows w*16..w*16+15
#define NCHUNKS 16                   // gate-col chunks (32 interleaved rows each)
#define XPITCH  400                  // bytes per X row (200 bf16)
#define CPITCH  129
#define WCHB    6144                 // one K-half chunk, hi (or lo) bytes: 6*2*32*16
#define WBUF    12288                // hi+lo per K-half chunk

// SMEM byte offsets (total 114208 -> 2 CTAs/SM)
#define SM_XH 0                      // 64 x 400 = 25600
#define SM_XL 25600                  // 25600
#define SM_WB 51200                  // 2 x WBUF = 24576
#define SM_C  75776                  // 64 x 129 x 4 = 33024
#define SM_F  108800                 // 1352 floats = 5408
#define SMEM_TOTAL 114208

// ---- static device scratch ----
// W fragments: 32 load-chunks (nc,kh), each [kk6(6)][nh(2)][lane(32)] uint4
__device__ uint4 g_WFH[32 * 6 * 2 * 32];
__device__ uint4 g_WFL[32 * 6 * 2 * 32];

__global__ void prep_frag(const float* __restrict__ Wih, const float* __restrict__ Whh) {
    int idx = blockIdx.x * blockDim.x + threadIdx.x;   // 49152 uint32 words
    if (idx >= 32 * 6 * 2 * 32 * 4) return;
    int r    = idx & 3;
    int lane = (idx >> 2) & 31;
    int nh   = (idx >> 7) & 1;
    int tmp  = idx >> 8;          // [nc(16)][kh(2)][kk6(6)]
    int kk6  = tmp % 6;
    int kh   = (tmp / 6) & 1;
    int nc   = tmp / 12;
    int q = r >> 1, rr = r & 1;
    int np = nc * 32 + nh * 16 + q * 8 + (lane >> 2);   // gate-interleaved row j*4+g
    int kk = kh * 6 + kk6;
    int k0 = kk * 16 + (lane & 3) * 2 + rr * 8;
    int col = (np & 3) * 128 + (np >> 2);               // g*128 + j
    float w0 = (k0 < 64) ? Wih[k0 * 512 + col] : Whh[(k0 - 64) * 512 + col];
    int k1 = k0 + 1;
    float w1 = (k1 < 64) ? Wih[k1 * 512 + col] : Whh[(k1 - 64) * 512 + col];
    __nv_bfloat16 h0 = __float2bfloat16(w0);
    __nv_bfloat16 h1 = __float2bfloat16(w1);
    __nv_bfloat16 l0 = __float2bfloat16(w0 - __bfloat162float(h0));
    __nv_bfloat16 l1 = __float2bfloat16(w1 - __bfloat162float(h1));
    // dest word index: ((((nc*2+kh)*6 + kk6)*2 + nh)*32 + lane)*4 + r
    int dw = ((((nc * 2 + kh) * 6 + kk6) * 2 + nh) * 32 + lane) * 4 + r;
    ((uint32_t*)g_WFH)[dw] = (uint32_t)__bfloat16_as_ushort(h0) | ((uint32_t)__bfloat16_as_ushort(h1) << 16);
    ((uint32_t*)g_WFL)[dw] = (uint32_t)__bfloat16_as_ushort(l0) | ((uint32_t)__bfloat16_as_ushort(l1) << 16);
}

__device__ __forceinline__ uint32_t smem_u32(const void* p) {
    uint32_t a;
    asm("{ .reg .u64 t; cvta.to.shared.u64 t, %1; cvt.u32.u64 %0, t; }" : "=r"(a) : "l"(p));
    return a;
}
__device__ __forceinline__ void ldsm4(uint32_t& r0, uint32_t& r1, uint32_t& r2, uint32_t& r3, uint32_t addr) {
    asm volatile("ldmatrix.sync.aligned.m8n8.x4.shared.b16 {%0,%1,%2,%3}, [%4];"
                 : "=r"(r0), "=r"(r1), "=r"(r2), "=r"(r3) : "r"(addr));
}
__device__ __forceinline__ void mma16816b(float* d, const uint32_t* a, uint32_t b0, uint32_t b1) {
    asm volatile("mma.sync.aligned.m16n8k16.row.col.f32.bf16.bf16.f32 "
                 "{%0,%1,%2,%3},{%4,%5,%6,%7},{%8,%9},{%0,%1,%2,%3};"
                 : "+f"(d[0]), "+f"(d[1]), "+f"(d[2]), "+f"(d[3])
                 : "r"(a[0]), "r"(a[1]), "r"(a[2]), "r"(a[3]), "r"(b0), "r"(b1));
}
__device__ __forceinline__ void cpasync16(uint32_t dst, const void* src) {
    asm volatile("cp.async.cg.shared.global [%0], [%1], 16;" :: "r"(dst), "l"(src) : "memory");
}
#define CP_COMMIT() asm volatile("cp.async.commit_group;" ::: "memory")
#define CP_WAIT0()  asm volatile("cp.async.wait_group 0;" ::: "memory")

__device__ __forceinline__ float tanh_apx(float x) {
    float y;
    asm("tanh.approx.f32 %0, %1;" : "=f"(y) : "f"(x));
    return y;
}
__device__ __forceinline__ float sigm(float x) { return fmaf(0.5f, tanh_apx(0.5f * x), 0.5f); }
__device__ __forceinline__ void bf16_split(float v, unsigned short& hi, unsigned short& lo) {
    __nv_bfloat16 h = __float2bfloat16(v);
    hi = __bfloat16_as_ushort(h);
    lo = __bfloat16_as_ushort(__float2bfloat16(v - __bfloat162float(h)));
}

__global__ __launch_bounds__(NTHREADS, 2)
void vlstm_mma(const float* __restrict__ nodes,
               const int* __restrict__ mask,
               const float* __restrict__ h0,
               const float* __restrict__ c0,
               const float* __restrict__ We,
               const float* __restrict__ be,
               const float* __restrict__ bih,
               const float* __restrict__ bhh,
               const float* __restrict__ Wout,
               const float* __restrict__ bout,
               float* __restrict__ out,
               float* __restrict__ hfin,
               float* __restrict__ cfin) {
    extern __shared__ char smem[];
    float* sc    = (float*)(smem + SM_C);
    float* sBias = (float*)(smem + SM_F);   // 512
    float* sWe   = sBias + 512;
    float* sBe   = sWe + 128;
    float* sWout = sBe + 64;
    float* sBout = sWout + 640;

    const int tid  = threadIdx.x;
    const int wid  = tid >> 5, lane = tid & 31;
    const int base = blockIdx.x * TILE_N;
    const uint32_t sbase = smem_u32(smem);

    for (int i = tid; i < 512; i += NTHREADS) sBias[i] = bih[i] + bhh[i];
    if (tid < 128) sWe[tid] = We[tid];
    if (tid < 64)  sBe[tid] = be[tid];
    for (int i = tid; i < 640; i += NTHREADS) sWout[i] = Wout[i];
    if (tid < 5) sBout[tid] = bout[tid];
    for (int idx = tid; idx < TILE_N * DH; idx += NTHREADS) {
        int n = idx >> 7, j = idx & 127;
        unsigned short hb, lb;
        bf16_split(h0[(size_t)(base + n) * DH + j], hb, lb);
        *(unsigned short*)(smem + SM_XH + n * XPITCH + 128 + 2 * j) = hb;
        *(unsigned short*)(smem + SM_XL + n * XPITCH + 128 + 2 * j) = lb;
        sc[n * CPITCH + j] = c0[(size_t)(base + n) * DH + j];
    }
    __syncthreads();

    const int mt = wid;                       // warp owns rows mt*16..mt*16+15
    const uint32_t aoff = (uint32_t)((lane & 7) + ((lane >> 3) & 1) * 8) * XPITCH
                        + (uint32_t)(lane >> 4) * 16;
    const uint32_t xhBase = sbase + SM_XH + (uint32_t)mt * 16 * XPITCH;
    const uint32_t xlBase = sbase + SM_XL + (uint32_t)mt * 16 * XPITCH;
    const int p4 = lane & 3, odd = p4 & 1;
    const int row = mt * 16 + (lane >> 2) + odd * 8;
    const int node = base + row;
    const int erow = mt * 16 + (lane >> 1);
    const int ekb  = (lane & 1) * 32;

    #define EPILOGUE(ACC, NCE)                                                       \
    {                                                                                \
        _Pragma("unroll")                                                            \
        for (int nh = 0; nh < 2; nh++) {                                             \
            _Pragma("unroll")                                                        \
            for (int q = 0; q < 2; q++) {                                            \
                float* d = (ACC) + (nh * 2 + q) * 4;                                 \
                float v0 = odd ? d[0] : d[2];                                        \
                float v1 = odd ? d[1] : d[3];                                        \
                float r0 = __shfl_xor_sync(0xffffffffu, v0, 1);                      \
                float r1 = __shfl_xor_sync(0xffffffffu, v1, 1);                      \
                float gi, gf, gg, go;                                                \
                if (!odd) { gi = d[0]; gf = d[1]; gg = r0; go = r1; }                 \
                else      { gi = r0;   gf = r1;   gg = d[2]; go = d[3]; }             \
                int j = (NCE) * 8 + nh * 4 + q * 2 + (p4 >> 1);                      \
                float cold = sc[row * CPITCH + j];                                   \
                float iv = sigm(gi + sBias[j]);                                      \
                float fv = sigm(gf + sBias[128 + j]);                                \
                float gv = tanh_apx(gg + sBias[256 + j]);                            \
                float ov = sigm(go + sBias[384 + j]);                                \
                float cn = fmaf(fv, cold, iv * gv);                                  \
                float hn = ov * tanh_apx(cn);                                        \
                sc[row * CPITCH + j] = act ? cn : cold;                              \
                float hg = act ? hn : 0.0f;                                          \
                if (act) {                                                           \
                    unsigned short hb, lb;                                           \
                    bf16_split(hn, hb, lb);                                          \
                    *(unsigned short*)(smem + SM_XH + row * XPITCH + 128 + 2 * j) = hb; \
                    *(unsigned short*)(smem + SM_XL + row * XPITCH + 128 + 2 * j) = lb; \
                }                                                                    \
                const float* w0 = sWout + j * 5;                                     \
                oacc[0] = fmaf(hg, w0[0], oacc[0]);                                  \
                oacc[1] = fmaf(hg, w0[1], oacc[1]);                                  \
                oacc[2] = fmaf(hg, w0[2], oacc[2]);                                  \
                oacc[3] = fmaf(hg, w0[3], oacc[3]);                                  \
                oacc[4] = fmaf(hg, w0[4], oacc[4]);                                  \
            }                                                                        \
        }                                                                            \
    }

    // One K-half (6 kk) of a gate-chunk. 12 MMAs/kk6 over 4 acc chains.
    #define MMA_HALF(ACC, BUF, KH, ZERO)                                             \
    {                                                                                \
        const char* wch = smem + SM_WB + (BUF) * WBUF;                               \
        if (ZERO) {                                                                  \
            _Pragma("unroll")                                                        \
            for (int z = 0; z < 16; z++) (ACC)[z] = 0.0f;                            \
        }                                                                            \
        uint4 nh0 = *(const uint4*)(wch + lane * 16);                                \
        uint4 nh1 = *(const uint4*)(wch + (32 + lane) * 16);                         \
        uint4 nl0 = *(const uint4*)(wch + WCHB + lane * 16);                         \
        uint4 nl1 = *(const uint4*)(wch + WCHB + (32 + lane) * 16);                  \
        _Pragma("unroll")                                                            \
        for (int kk6 = 0; kk6 < 6; kk6++) {                                          \
            uint4 ch0 = nh0, ch1 = nh1, cl0 = nl0, cl1 = nl1;                        \
            if (kk6 < 5) {                                                           \
                int o = ((kk6 + 1) * 64 + lane) * 16;                                \
                nh0 = *(const uint4*)(wch + o);                                      \
                nh1 = *(const uint4*)(wch + o + 512);                                \
                nl0 = *(const uint4*)(wch + WCHB + o);                               \
                nl1 = *(const uint4*)(wch + WCHB + o + 512);                         \
            }                                                                        \
            const uint32_t* ah = AH[(KH) * 6 + kk6];                                 \
            const uint32_t* al = AL[(KH) * 6 + kk6];                                 \
            mma16816b((ACC) + 0,  ah, ch0.x, ch0.y);                                 \
            mma16816b((ACC) + 4,  ah, ch0.z, ch0.w);                                 \
            mma16816b((ACC) + 8,  ah, ch1.x, ch1.y);                                 \
            mma16816b((ACC) + 12, ah, ch1.z, ch1.w);                                 \
            mma16816b((ACC) + 0,  al, ch0.x, ch0.y);                                 \
            mma16816b((ACC) + 4,  al, ch0.z, ch0.w);                                 \
            mma16816b((ACC) + 8,  al, ch1.x, ch1.y);                                 \
            mma16816b((ACC) + 12, al, ch1.z, ch1.w);                                 \
            mma16816b((ACC) + 0,  ah, cl0.x, cl0.y);                                 \
            mma16816b((ACC) + 4,  ah, cl0.z, cl0.w);                                 \
            mma16816b((ACC) + 8,  ah, cl1.x, cl1.y);                                 \
            mma16816b((ACC) + 12, ah, cl1.z, cl1.w);                                 \
        }                                                                            \
    }

    // Prefetch load-chunk C (C = nc*2 + kh, 0..31) into buffer C&1
    #define PREFETCH_W(C)                                                            \
    {                                                                                \
        uint32_t dst = sbase + SM_WB + ((C) & 1) * WBUF;                             \
        const char* srcH = (const char*)g_WFH + (C) * WCHB;                          \
        const char* srcL = (const char*)g_WFL + (C) * WCHB;                          \
        _Pragma("unroll")                                                            \
        for (int i = 0; i < 3; i++) {                                                \
            int o = tid * 16 + i * 2048;                                             \
            cpasync16(dst + o, srcH + o);                                            \
            cpasync16(dst + WCHB + o, srcL + o);                                     \
        }                                                                            \
        CP_COMMIT();                                                                 \
    }

    for (int t = 0; t < T_STEPS; t++) {
        const int act = mask[(size_t)t * N_NODES + node];

        // emb rebuild (warp-private rows), packed 32-bit stores
        {
            float2 xy = ((const float2*)nodes)[(size_t)t * N_NODES + base + erow];
            #pragma unroll 4
            for (int i = 0; i < 16; i++) {
                int k = ekb + 2 * i;
                float e0 = fmaxf(fmaf(xy.x, sWe[k], fmaf(xy.y, sWe[64 + k], sBe[k])), 0.0f);
                float e1 = fmaxf(fmaf(xy.x, sWe[k + 1], fmaf(xy.y, sWe[64 + k + 1], sBe[k + 1])), 0.0f);
                unsigned short h0b, l0b, h1b, l1b;
                bf16_split(e0, h0b, l0b);
                bf16_split(e1, h1b, l1b);
                *(uint32_t*)(smem + SM_XH + erow * XPITCH + 2 * k) = (uint32_t)h0b | ((uint32_t)h1b << 16);
                *(uint32_t*)(smem + SM_XL + erow * XPITCH + 2 * k) = (uint32_t)l0b | ((uint32_t)l1b << 16);
            }
        }
        __syncwarp();

        PREFETCH_W(0)

        // load A fragments once per step (register-resident X)
        uint32_t AH[12][4], AL[12][4];
        #pragma unroll
        for (int kk = 0; kk < 12; kk++) {
            ldsm4(AH[kk][0], AH[kk][1], AH[kk][2], AH[kk][3], xhBase + aoff + kk * 32);
            ldsm4(AL[kk][0], AL[kk][1], AL[kk][2], AL[kk][3], xlBase + aoff + kk * 32);
        }

        float oacc[5] = {0.f, 0.f, 0.f, 0.f, 0.f};
        float accA[16], accB[16];

        // pipelined chunk loop: chunk nc split into K-halves, epilogue(nc-1)
        // overlapped with first K-half MMAs of nc
        for (int nc2 = 0; nc2 < NCHUNKS; nc2 += 2) {
            // even chunk -> accA
            CP_WAIT0();
            __syncthreads();
            PREFETCH_W(2 * nc2 + 1)
            MMA_HALF(accA, 0, 0, true)
            if (nc2 > 0) EPILOGUE(accB, nc2 - 1)
            CP_WAIT0();
            __syncthreads();
            PREFETCH_W(2 * nc2 + 2)
            MMA_HALF(accA, 1, 1, false)
            // odd chunk -> accB
            CP_WAIT0();
            __syncthreads();
            PREFETCH_W(2 * nc2 + 3)
            MMA_HALF(accB, 0, 0, true)
            EPILOGUE(accA, nc2)
            CP_WAIT0();
            __syncthreads();
            if (2 * nc2 + 4 < 32) PREFETCH_W(2 * nc2 + 4)
            MMA_HALF(accB, 1, 1, false)
        }
        EPILOGUE(accB, NCHUNKS - 1)

        // combine j-halves and write out
        float comb[5];
        #pragma unroll
        for (int z = 0; z < 5; z++)
            comb[z] = oacc[z] + __shfl_xor_sync(0xffffffffu, oacc[z], 2);
        if (p4 < 2) {
            float* op = out + ((size_t)t * N_NODES + node) * 5;
            if (act) {
                op[0] = comb[0] + sBout[0];
                op[1] = comb[1] + sBout[1];
                op[2] = comb[2] + sBout[2];
                op[3] = comb[3] + sBout[3];
                op[4] = comb[4] + sBout[4];
            } else {
                op[0] = 0.f; op[1] = 0.f; op[2] = 0.f; op[3] = 0.f; op[4] = 0.f;
            }
        }
    }

    __syncthreads();
    for (int idx = tid; idx < TILE_N * DH; idx += NTHREADS) {
        int n = idx >> 7, j = idx & 127;
        float hv = __bfloat162float(__ushort_as_bfloat16(
                       *(unsigned short*)(smem + SM_XH + n * XPITCH + 128 + 2 * j)))
                 + __bfloat162float(__ushort_as_bfloat16(
                       *(unsigned short*)(smem + SM_XL + n * XPITCH + 128 + 2 * j)));
        hfin[(size_t)(base + n) * DH + j] = hv;
        cfin[(size_t)(base + n) * DH + j] = sc[n * CPITCH + j];
    }
}

extern "C" void kernel_launch(void* const* d_in, const int* in_sizes, int n_in,
                              void* d_out, int out_size) {
    const float* nodes = (const float*)d_in[0];
    const int* mask    = (const int*)d_in[1];
    const float* h0    = (const float*)d_in[2];
    const float* c0    = (const float*)d_in[3];
    const float* We    = (const float*)d_in[4];
    const float* be    = (const float*)d_in[5];
    const float* Wih   = (const float*)d_in[6];
    const float* bih   = (const float*)d_in[7];
    const float* Whh   = (const float*)d_in[8];
    const float* bhh   = (const float*)d_in[9];
    const float* Wout  = (const float*)d_in[10];
    const float* bout  = (const float*)d_in[11];

    float* out  = (float*)d_out;
    float* hfin = out + (size_t)T_STEPS * N_NODES * 5;
    float* cfin = hfin + (size_t)N_NODES * DH;

    prep_frag<<<(32 * 6 * 2 * 32 * 4 + 255) / 256, 256>>>(Wih, Whh);

    cudaFuncSetAttribute(vlstm_mma, cudaFuncAttributeMaxDynamicSharedMemorySize, SMEM_TOTAL);
    vlstm_mma<<<NBLOCKS, NTHREADS, SMEM_TOTAL>>>(
        nodes, mask, h0, c0, We, be, bih, bhh, Wout, bout, out, hfin, cfin);
}

// round 14
// speedup vs baseline: 1.6837x; 1.3396x over previous
#include <cuda_runtime.h>
#include <cuda_fp16.h>
#include <cstdint>

#define T_STEPS 20
#define N_NODES 32768
#define TILE_N  64
#define DH      128
#define NBLOCKS (N_NODES / TILE_N)   // 512
#define NTHREADS 128                 // 4 warps; warp w owns rows w*16..w*16+15
#define NCHUNKS 16                   // gate-col chunks (32 interleaved rows each)
#define XPITCH  400                  // bytes per X row (200 fp16)
#define CPITCH  129
#define WCHB    6144                 // one K-half chunk bytes: 6*2*32*16
#define WBUF    6144                 // single (hi-only) buffer per K-half chunk

// SMEM byte offsets (total 101920 -> 2 CTAs/SM)
#define SM_XH 0                      // 64 x 400 = 25600
#define SM_XL 25600                  // 25600
#define SM_WB 51200                  // 2 x WBUF = 12288
#define SM_C  63488                  // 64 x 129 x 4 = 33024
#define SM_F  96512                  // 1352 floats = 5408
#define SMEM_TOTAL 101920

// ---- static device scratch ----
// W fp16 fragments: 32 load-chunks (nc,kh), each [kk6(6)][nh(2)][lane(32)] uint4
__device__ uint4 g_WF[32 * 6 * 2 * 32];

__global__ void prep_frag(const float* __restrict__ Wih, const float* __restrict__ Whh) {
    int idx = blockIdx.x * blockDim.x + threadIdx.x;   // 49152 uint32 words
    if (idx >= 32 * 6 * 2 * 32 * 4) return;
    int r    = idx & 3;
    int lane = (idx >> 2) & 31;
    int nh   = (idx >> 7) & 1;
    int tmp  = idx >> 8;          // [nc(16)][kh(2)][kk6(6)]
    int kk6  = tmp % 6;
    int kh   = (tmp / 6) & 1;
    int nc   = tmp / 12;
    int q = r >> 1, rr = r & 1;
    int np = nc * 32 + nh * 16 + q * 8 + (lane >> 2);   // gate-interleaved row j*4+g
    int kk = kh * 6 + kk6;
    int k0 = kk * 16 + (lane & 3) * 2 + rr * 8;
    int col = (np & 3) * 128 + (np >> 2);               // g*128 + j
    float w0 = (k0 < 64) ? Wih[k0 * 512 + col] : Whh[(k0 - 64) * 512 + col];
    int k1 = k0 + 1;
    float w1 = (k1 < 64) ? Wih[k1 * 512 + col] : Whh[(k1 - 64) * 512 + col];
    unsigned short a = __half_as_ushort(__float2half_rn(w0));
    unsigned short b = __half_as_ushort(__float2half_rn(w1));
    int dw = ((((nc * 2 + kh) * 6 + kk6) * 2 + nh) * 32 + lane) * 4 + r;
    ((uint32_t*)g_WF)[dw] = (uint32_t)a | ((uint32_t)b << 16);
}

__device__ __forceinline__ uint32_t smem_u32(const void* p) {
    uint32_t a;
    asm("{ .reg .u64 t; cvta.to.shared.u64 t, %1; cvt.u32.u64 %0, t; }" : "=r"(a) : "l"(p));
    return a;
}
__device__ __forceinline__ void ldsm4(uint32_t& r0, uint32_t& r1, uint32_t& r2, uint32_t& r3, uint32_t addr) {
    asm volatile("ldmatrix.sync.aligned.m8n8.x4.shared.b16 {%0,%1,%2,%3}, [%4];"
                 : "=r"(r0), "=r"(r1), "=r"(r2), "=r"(r3) : "r"(addr));
}
__device__ __forceinline__ void mma16816h(float* d, const uint32_t* a, uint32_t b0, uint32_t b1) {
    asm volatile("mma.sync.aligned.m16n8k16.row.col.f32.f16.f16.f32 "
                 "{%0,%1,%2,%3},{%4,%5,%6,%7},{%8,%9},{%0,%1,%2,%3};"
                 : "+f"(d[0]), "+f"(d[1]), "+f"(d[2]), "+f"(d[3])
                 : "r"(a[0]), "r"(a[1]), "r"(a[2]), "r"(a[3]), "r"(b0), "r"(b1));
}
__device__ __forceinline__ void cpasync16(uint32_t dst, const void* src) {
    asm volatile("cp.async.cg.shared.global [%0], [%1], 16;" :: "r"(dst), "l"(src) : "memory");
}
#define CP_COMMIT() asm volatile("cp.async.commit_group;" ::: "memory")
#define CP_WAIT0()  asm volatile("cp.async.wait_group 0;" ::: "memory")

__device__ __forceinline__ float tanh_apx(float x) {
    float y;
    asm("tanh.approx.f32 %0, %1;" : "=f"(y) : "f"(x));
    return y;
}
__device__ __forceinline__ float sigm(float x) { return fmaf(0.5f, tanh_apx(0.5f * x), 0.5f); }
__device__ __forceinline__ void fp16_split(float v, unsigned short& hi, unsigned short& lo) {
    __half h = __float2half_rn(v);
    hi = __half_as_ushort(h);
    lo = __half_as_ushort(__float2half_rn(v - __half2float(h)));
}

__global__ __launch_bounds__(NTHREADS, 2)
void vlstm_mma(const float* __restrict__ nodes,
               const int* __restrict__ mask,
               const float* __restrict__ h0,
               const float* __restrict__ c0,
               const float* __restrict__ We,
               const float* __restrict__ be,
               const float* __restrict__ bih,
               const float* __restrict__ bhh,
               const float* __restrict__ Wout,
               const float* __restrict__ bout,
               float* __restrict__ out,
               float* __restrict__ hfin,
               float* __restrict__ cfin) {
    extern __shared__ char smem[];
    float* sc    = (float*)(smem + SM_C);
    float* sBias = (float*)(smem + SM_F);   // 512
    float* sWe   = sBias + 512;
    float* sBe   = sWe + 128;
    float* sWout = sBe + 64;
    float* sBout = sWout + 640;

    const int tid  = threadIdx.x;
    const int wid  = tid >> 5, lane = tid & 31;
    const int base = blockIdx.x * TILE_N;
    const uint32_t sbase = smem_u32(smem);

    for (int i = tid; i < 512; i += NTHREADS) sBias[i] = bih[i] + bhh[i];
    if (tid < 128) sWe[tid] = We[tid];
    if (tid < 64)  sBe[tid] = be[tid];
    for (int i = tid; i < 640; i += NTHREADS) sWout[i] = Wout[i];
    if (tid < 5) sBout[tid] = bout[tid];
    for (int idx = tid; idx < TILE_N * DH; idx += NTHREADS) {
        int n = idx >> 7, j = idx & 127;
        unsigned short hb, lb;
        fp16_split(h0[(size_t)(base + n) * DH + j], hb, lb);
        *(unsigned short*)(smem + SM_XH + n * XPITCH + 128 + 2 * j) = hb;
        *(unsigned short*)(smem + SM_XL + n * XPITCH + 128 + 2 * j) = lb;
        sc[n * CPITCH + j] = c0[(size_t)(base + n) * DH + j];
    }
    __syncthreads();

    const int mt = wid;                       // warp owns rows mt*16..mt*16+15
    const uint32_t aoff = (uint32_t)((lane & 7) + ((lane >> 3) & 1) * 8) * XPITCH
                        + (uint32_t)(lane >> 4) * 16;
    const uint32_t xhBase = sbase + SM_XH + (uint32_t)mt * 16 * XPITCH;
    const uint32_t xlBase = sbase + SM_XL + (uint32_t)mt * 16 * XPITCH;
    const int p4 = lane & 3, odd = p4 & 1;
    const int row = mt * 16 + (lane >> 2) + odd * 8;
    const int node = base + row;
    const int erow = mt * 16 + (lane >> 1);
    const int ekb  = (lane & 1) * 32;

    #define EPILOGUE(ACC, NCE)                                                       \
    {                                                                                \
        _Pragma("unroll")                                                            \
        for (int nh = 0; nh < 2; nh++) {                                             \
            _Pragma("unroll")                                                        \
            for (int q = 0; q < 2; q++) {                                            \
                float* d = (ACC) + (nh * 2 + q) * 4;                                 \
                float v0 = odd ? d[0] : d[2];                                        \
                float v1 = odd ? d[1] : d[3];                                        \
                float r0 = __shfl_xor_sync(0xffffffffu, v0, 1);                      \
                float r1 = __shfl_xor_sync(0xffffffffu, v1, 1);                      \
                float gi, gf, gg, go;                                                \
                if (!odd) { gi = d[0]; gf = d[1]; gg = r0; go = r1; }                 \
                else      { gi = r0;   gf = r1;   gg = d[2]; go = d[3]; }             \
                int j = (NCE) * 8 + nh * 4 + q * 2 + (p4 >> 1);                      \
                float cold = sc[row * CPITCH + j];                                   \
                float iv = sigm(gi + sBias[j]);                                      \
                float fv = sigm(gf + sBias[128 + j]);                                \
                float gv = tanh_apx(gg + sBias[256 + j]);                            \
                float ov = sigm(go + sBias[384 + j]);                                \
                float cn = fmaf(fv, cold, iv * gv);                                  \
                float hn = ov * tanh_apx(cn);                                        \
                sc[row * CPITCH + j] = act ? cn : cold;                              \
                float hg = act ? hn : 0.0f;                                          \
                if (act) {                                                           \
                    unsigned short hb, lb;                                           \
                    fp16_split(hn, hb, lb);                                          \
                    *(unsigned short*)(smem + SM_XH + row * XPITCH + 128 + 2 * j) = hb; \
                    *(unsigned short*)(smem + SM_XL + row * XPITCH + 128 + 2 * j) = lb; \
                }                                                                    \
                const float* w0 = sWout + j * 5;                                     \
                oacc[0] = fmaf(hg, w0[0], oacc[0]);                                  \
                oacc[1] = fmaf(hg, w0[1], oacc[1]);                                  \
                oacc[2] = fmaf(hg, w0[2], oacc[2]);                                  \
                oacc[3] = fmaf(hg, w0[3], oacc[3]);                                  \
                oacc[4] = fmaf(hg, w0[4], oacc[4]);                                  \
            }                                                                        \
        }                                                                            \
    }

    // One K-half (6 kk) of a gate-chunk. 8 MMAs/kk6 over 4 acc chains.
    #define MMA_HALF(ACC, BUF, KH, ZERO)                                             \
    {                                                                                \
        const char* wch = smem + SM_WB + (BUF) * WBUF;                               \
        if (ZERO) {                                                                  \
            _Pragma("unroll")                                                        \
            for (int z = 0; z < 16; z++) (ACC)[z] = 0.0f;                            \
        }                                                                            \
        uint4 nh0 = *(const uint4*)(wch + lane * 16);                                \
        uint4 nh1 = *(const uint4*)(wch + (32 + lane) * 16);                         \
        _Pragma("unroll")                                                            \
        for (int kk6 = 0; kk6 < 6; kk6++) {                                          \
            uint4 ch0 = nh0, ch1 = nh1;                                              \
            if (kk6 < 5) {                                                           \
                int o = ((kk6 + 1) * 64 + lane) * 16;                                \
                nh0 = *(const uint4*)(wch + o);                                      \
                nh1 = *(const uint4*)(wch + o + 512);                                \
            }                                                                        \
            const uint32_t* ah = AH[(KH) * 6 + kk6];                                 \
            const uint32_t* al = AL[(KH) * 6 + kk6];                                 \
            mma16816h((ACC) + 0,  ah, ch0.x, ch0.y);                                 \
            mma16816h((ACC) + 4,  ah, ch0.z, ch0.w);                                 \
            mma16816h((ACC) + 8,  ah, ch1.x, ch1.y);                                 \
            mma16816h((ACC) + 12, ah, ch1.z, ch1.w);                                 \
            mma16816h((ACC) + 0,  al, ch0.x, ch0.y);                                 \
            mma16816h((ACC) + 4,  al, ch0.z, ch0.w);                                 \
            mma16816h((ACC) + 8,  al, ch1.x, ch1.y);                                 \
            mma16816h((ACC) + 12, al, ch1.z, ch1.w);                                 \
        }                                                                            \
    }

    // Prefetch load-chunk C (C = nc*2 + kh, 0..31) into buffer C&1
    #define PREFETCH_W(C)                                                            \
    {                                                                                \
        uint32_t dst = sbase + SM_WB + ((C) & 1) * WBUF;                             \
        const char* srcW = (const char*)g_WF + (C) * WCHB;                           \
        _Pragma("unroll")                                                            \
        for (int i = 0; i < 3; i++) {                                                \
            int o = tid * 16 + i * 2048;                                             \
            cpasync16(dst + o, srcW + o);                                            \
        }                                                                            \
        CP_COMMIT();                                                                 \
    }

    for (int t = 0; t < T_STEPS; t++) {
        const int act = mask[(size_t)t * N_NODES + node];

        // emb rebuild (warp-private rows), packed 32-bit stores
        {
            float2 xy = ((const float2*)nodes)[(size_t)t * N_NODES + base + erow];
            #pragma unroll 4
            for (int i = 0; i < 16; i++) {
                int k = ekb + 2 * i;
                float e0 = fmaxf(fmaf(xy.x, sWe[k], fmaf(xy.y, sWe[64 + k], sBe[k])), 0.0f);
                float e1 = fmaxf(fmaf(xy.x, sWe[k + 1], fmaf(xy.y, sWe[64 + k + 1], sBe[k + 1])), 0.0f);
                unsigned short h0b, l0b, h1b, l1b;
                fp16_split(e0, h0b, l0b);
                fp16_split(e1, h1b, l1b);
                *(uint32_t*)(smem + SM_XH + erow * XPITCH + 2 * k) = (uint32_t)h0b | ((uint32_t)h1b << 16);
                *(uint32_t*)(smem + SM_XL + erow * XPITCH + 2 * k) = (uint32_t)l0b | ((uint32_t)l1b << 16);
            }
        }
        __syncwarp();

        PREFETCH_W(0)

        // load A fragments once per step (register-resident X)
        uint32_t AH[12][4], AL[12][4];
        #pragma unroll
        for (int kk = 0; kk < 12; kk++) {
            ldsm4(AH[kk][0], AH[kk][1], AH[kk][2], AH[kk][3], xhBase + aoff + kk * 32);
            ldsm4(AL[kk][0], AL[kk][1], AL[kk][2], AL[kk][3], xlBase + aoff + kk * 32);
        }

        float oacc[5] = {0.f, 0.f, 0.f, 0.f, 0.f};
        float accA[16], accB[16];

        // pipelined chunk loop: chunk nc split into K-halves, epilogue(nc-1)
        // overlapped with first K-half MMAs of nc
        for (int nc2 = 0; nc2 < NCHUNKS; nc2 += 2) {
            // even chunk -> accA
            CP_WAIT0();
            __syncthreads();
            PREFETCH_W(2 * nc2 + 1)
            MMA_HALF(accA, 0, 0, true)
            if (nc2 > 0) EPILOGUE(accB, nc2 - 1)
            CP_WAIT0();
            __syncthreads();
            PREFETCH_W(2 * nc2 + 2)
            MMA_HALF(accA, 1, 1, false)
            // odd chunk -> accB
            CP_WAIT0();
            __syncthreads();
            PREFETCH_W(2 * nc2 + 3)
            MMA_HALF(accB, 0, 0, true)
            EPILOGUE(accA, nc2)
            CP_WAIT0();
            __syncthreads();
            if (2 * nc2 + 4 < 32) PREFETCH_W(2 * nc2 + 4)
            MMA_HALF(accB, 1, 1, false)
        }
        EPILOGUE(accB, NCHUNKS - 1)

        // combine j-halves and write out
        float comb[5];
        #pragma unroll
        for (int z = 0; z < 5; z++)
            comb[z] = oacc[z] + __shfl_xor_sync(0xffffffffu, oacc[z], 2);
        if (p4 < 2) {
            float* op = out + ((size_t)t * N_NODES + node) * 5;
            if (act) {
                op[0] = comb[0] + sBout[0];
                op[1] = comb[1] + sBout[1];
                op[2] = comb[2] + sBout[2];
                op[3] = comb[3] + sBout[3];
                op[4] = comb[4] + sBout[4];
            } else {
                op[0] = 0.f; op[1] = 0.f; op[2] = 0.f; op[3] = 0.f; op[4] = 0.f;
            }
        }
    }

    __syncthreads();
    for (int idx = tid; idx < TILE_N * DH; idx += NTHREADS) {
        int n = idx >> 7, j = idx & 127;
        float hv = __half2float(__ushort_as_half(
                       *(unsigned short*)(smem + SM_XH + n * XPITCH + 128 + 2 * j)))
                 + __half2float(__ushort_as_half(
                       *(unsigned short*)(smem + SM_XL + n * XPITCH + 128 + 2 * j)));
        hfin[(size_t)(base + n) * DH + j] = hv;
        cfin[(size_t)(base + n) * DH + j] = sc[n * CPITCH + j];
    }
}

extern "C" void kernel_launch(void* const* d_in, const int* in_sizes, int n_in,
                              void* d_out, int out_size) {
    const float* nodes = (const float*)d_in[0];
    const int* mask    = (const int*)d_in[1];
    const float* h0    = (const float*)d_in[2];
    const float* c0    = (const float*)d_in[3];
    const float* We    = (const float*)d_in[4];
    const float* be    = (const float*)d_in[5];
    const float* Wih   = (const float*)d_in[6];
    const float* bih   = (const float*)d_in[7];
    const float* Whh   = (const float*)d_in[8];
    const float* bhh   = (const float*)d_in[9];
    const float* Wout  = (const float*)d_in[10];
    const float* bout  = (const float*)d_in[11];

    float* out  = (float*)d_out;
    float* hfin = out + (size_t)T_STEPS * N_NODES * 5;
    float* cfin = hfin + (size_t)N_NODES * DH;

    prep_frag<<<(32 * 6 * 2 * 32 * 4 + 255) / 256, 256>>>(Wih, Whh);

    cudaFuncSetAttribute(vlstm_mma, cudaFuncAttributeMaxDynamicSharedMemorySize, SMEM_TOTAL);
    vlstm_mma<<<NBLOCKS, NTHREADS, SMEM_TOTAL>>>(
        nodes, mask, h0, c0, We, be, bih, bhh, Wout, bout, out, hfin, cfin);
}

// round 15
// speedup vs baseline: 1.9688x; 1.1694x over previous
#include <cuda_runtime.h>
#include <cuda_fp16.h>
#include <cstdint>

#define T_STEPS 20
#define N_NODES 32768
#define TILE_N  64
#define DH      128
#define NBLOCKS (N_NODES / TILE_N)   // 512
#define NTHREADS 128                 // 4 warps; warp w owns rows w*16..w*16+15
#define NCHUNKS 16                   // gate-col chunks (32 interleaved rows each)
#define XPITCH  400                  // bytes per X row (200 fp16)
#define HLPITCH 256                  // bytes per h-lo shadow row (128 fp16)
#define CPITCH  129
#define WCHUNK  12288                // full chunk bytes: 12*2*32*16
#define WBUF    12288

// SMEM byte offsets (total 104992 -> 2 CTAs/SM)
#define SM_XH 0                      // 64 x 400 = 25600
#define SM_HL 25600                  // h lo shadow: 64 x 256 = 16384 (not used by MMA)
#define SM_WB 41984                  // 2 x WBUF = 24576
#define SM_C  66560                  // 64 x 129 x 4 = 33024
#define SM_F  99584                  // 1352 floats = 5408
#define SMEM_TOTAL 104992

// ---- static device scratch ----
// W fp16 fragments: [nc(16)][kh(2)][kk6(6)][nh(2)][lane(32)] uint4; one nc = 12288B contiguous
__device__ uint4 g_WF[32 * 6 * 2 * 32];

__global__ void prep_frag(const float* __restrict__ Wih, const float* __restrict__ Whh) {
    int idx = blockIdx.x * blockDim.x + threadIdx.x;   // 49152 uint32 words
    if (idx >= 32 * 6 * 2 * 32 * 4) return;
    int r    = idx & 3;
    int lane = (idx >> 2) & 31;
    int nh   = (idx >> 7) & 1;
    int tmp  = idx >> 8;          // [nc(16)][kh(2)][kk6(6)]
    int kk6  = tmp % 6;
    int kh   = (tmp / 6) & 1;
    int nc   = tmp / 12;
    int q = r >> 1, rr = r & 1;
    int np = nc * 32 + nh * 16 + q * 8 + (lane >> 2);   // gate-interleaved row j*4+g
    int kk = kh * 6 + kk6;
    int k0 = kk * 16 + (lane & 3) * 2 + rr * 8;
    int col = (np & 3) * 128 + (np >> 2);               // g*128 + j
    float w0 = (k0 < 64) ? Wih[k0 * 512 + col] : Whh[(k0 - 64) * 512 + col];
    int k1 = k0 + 1;
    float w1 = (k1 < 64) ? Wih[k1 * 512 + col] : Whh[(k1 - 64) * 512 + col];
    unsigned short a = __half_as_ushort(__float2half_rn(w0));
    unsigned short b = __half_as_ushort(__float2half_rn(w1));
    int dw = ((((nc * 2 + kh) * 6 + kk6) * 2 + nh) * 32 + lane) * 4 + r;
    ((uint32_t*)g_WF)[dw] = (uint32_t)a | ((uint32_t)b << 16);
}

__device__ __forceinline__ uint32_t smem_u32(const void* p) {
    uint32_t a;
    asm("{ .reg .u64 t; cvta.to.shared.u64 t, %1; cvt.u32.u64 %0, t; }" : "=r"(a) : "l"(p));
    return a;
}
__device__ __forceinline__ void ldsm4(uint32_t& r0, uint32_t& r1, uint32_t& r2, uint32_t& r3, uint32_t addr) {
    asm volatile("ldmatrix.sync.aligned.m8n8.x4.shared.b16 {%0,%1,%2,%3}, [%4];"
                 : "=r"(r0), "=r"(r1), "=r"(r2), "=r"(r3) : "r"(addr));
}
__device__ __forceinline__ void mma16816h(float* d, const uint32_t* a, uint32_t b0, uint32_t b1) {
    asm volatile("mma.sync.aligned.m16n8k16.row.col.f32.f16.f16.f32 "
                 "{%0,%1,%2,%3},{%4,%5,%6,%7},{%8,%9},{%0,%1,%2,%3};"
                 : "+f"(d[0]), "+f"(d[1]), "+f"(d[2]), "+f"(d[3])
                 : "r"(a[0]), "r"(a[1]), "r"(a[2]), "r"(a[3]), "r"(b0), "r"(b1));
}
__device__ __forceinline__ void cpasync16(uint32_t dst, const void* src) {
    asm volatile("cp.async.cg.shared.global [%0], [%1], 16;" :: "r"(dst), "l"(src) : "memory");
}
#define CP_COMMIT() asm volatile("cp.async.commit_group;" ::: "memory")
#define CP_WAIT0()  asm volatile("cp.async.wait_group 0;" ::: "memory")

__device__ __forceinline__ float tanh_apx(float x) {
    float y;
    asm("tanh.approx.f32 %0, %1;" : "=f"(y) : "f"(x));
    return y;
}
__device__ __forceinline__ float sigm(float x) { return fmaf(0.5f, tanh_apx(0.5f * x), 0.5f); }
__device__ __forceinline__ void fp16_split(float v, unsigned short& hi, unsigned short& lo) {
    __half h = __float2half_rn(v);
    hi = __half_as_ushort(h);
    lo = __half_as_ushort(__float2half_rn(v - __half2float(h)));
}

__global__ __launch_bounds__(NTHREADS, 2)
void vlstm_mma(const float* __restrict__ nodes,
               const int* __restrict__ mask,
               const float* __restrict__ h0,
               const float* __restrict__ c0,
               const float* __restrict__ We,
               const float* __restrict__ be,
               const float* __restrict__ bih,
               const float* __restrict__ bhh,
               const float* __restrict__ Wout,
               const float* __restrict__ bout,
               float* __restrict__ out,
               float* __restrict__ hfin,
               float* __restrict__ cfin) {
    extern __shared__ char smem[];
    float* sc    = (float*)(smem + SM_C);
    float* sBias = (float*)(smem + SM_F);   // 512
    float* sWe   = sBias + 512;
    float* sBe   = sWe + 128;
    float* sWout = sBe + 64;
    float* sBout = sWout + 640;

    const int tid  = threadIdx.x;
    const int wid  = tid >> 5, lane = tid & 31;
    const int base = blockIdx.x * TILE_N;
    const uint32_t sbase = smem_u32(smem);

    for (int i = tid; i < 512; i += NTHREADS) sBias[i] = bih[i] + bhh[i];
    if (tid < 128) sWe[tid] = We[tid];
    if (tid < 64)  sBe[tid] = be[tid];
    for (int i = tid; i < 640; i += NTHREADS) sWout[i] = Wout[i];
    if (tid < 5) sBout[tid] = bout[tid];
    for (int idx = tid; idx < TILE_N * DH; idx += NTHREADS) {
        int n = idx >> 7, j = idx & 127;
        unsigned short hb, lb;
        fp16_split(h0[(size_t)(base + n) * DH + j], hb, lb);
        *(unsigned short*)(smem + SM_XH + n * XPITCH + 128 + 2 * j) = hb;
        *(unsigned short*)(smem + SM_HL + n * HLPITCH + 2 * j) = lb;
        sc[n * CPITCH + j] = c0[(size_t)(base + n) * DH + j];
    }
    __syncthreads();

    const int mt = wid;                       // warp owns rows mt*16..mt*16+15
    const uint32_t aoff = (uint32_t)((lane & 7) + ((lane >> 3) & 1) * 8) * XPITCH
                        + (uint32_t)(lane >> 4) * 16;
    const uint32_t xhBase = sbase + SM_XH + (uint32_t)mt * 16 * XPITCH;
    const int p4 = lane & 3, odd = p4 & 1;
    const int row = mt * 16 + (lane >> 2) + odd * 8;
    const int node = base + row;
    const int erow = mt * 16 + (lane >> 1);
    const int ekb  = (lane & 1) * 32;

    #define EPILOGUE(ACC, NCE)                                                       \
    {                                                                                \
        _Pragma("unroll")                                                            \
        for (int nh = 0; nh < 2; nh++) {                                             \
            _Pragma("unroll")                                                        \
            for (int q = 0; q < 2; q++) {                                            \
                float* d = (ACC) + (nh * 2 + q) * 4;                                 \
                float v0 = odd ? d[0] : d[2];                                        \
                float v1 = odd ? d[1] : d[3];                                        \
                float r0 = __shfl_xor_sync(0xffffffffu, v0, 1);                      \
                float r1 = __shfl_xor_sync(0xffffffffu, v1, 1);                      \
                float gi, gf, gg, go;                                                \
                if (!odd) { gi = d[0]; gf = d[1]; gg = r0; go = r1; }                 \
                else      { gi = r0;   gf = r1;   gg = d[2]; go = d[3]; }             \
                int j = (NCE) * 8 + nh * 4 + q * 2 + (p4 >> 1);                      \
                float cold = sc[row * CPITCH + j];                                   \
                float iv = sigm(gi + sBias[j]);                                      \
                float fv = sigm(gf + sBias[128 + j]);                                \
                float gv = tanh_apx(gg + sBias[256 + j]);                            \
                float ov = sigm(go + sBias[384 + j]);                                \
                float cn = fmaf(fv, cold, iv * gv);                                  \
                float hn = ov * tanh_apx(cn);                                        \
                sc[row * CPITCH + j] = act ? cn : cold;                              \
                float hg = act ? hn : 0.0f;                                          \
                if (act) {                                                           \
                    unsigned short hb, lb;                                           \
                    fp16_split(hn, hb, lb);                                          \
                    *(unsigned short*)(smem + SM_XH + row * XPITCH + 128 + 2 * j) = hb; \
                    *(unsigned short*)(smem + SM_HL + row * HLPITCH + 2 * j) = lb;   \
                }                                                                    \
                const float* w0 = sWout + j * 5;                                     \
                oacc[0] = fmaf(hg, w0[0], oacc[0]);                                  \
                oacc[1] = fmaf(hg, w0[1], oacc[1]);                                  \
                oacc[2] = fmaf(hg, w0[2], oacc[2]);                                  \
                oacc[3] = fmaf(hg, w0[3], oacc[3]);                                  \
                oacc[4] = fmaf(hg, w0[4], oacc[4]);                                  \
            }                                                                        \
        }                                                                            \
    }

    // Full chunk (12 kk): 4 MMAs per kk over 4 acc chains, single-fp16 A.
    #define MMA_CHUNK(ACC, BUF)                                                      \
    {                                                                                \
        const char* wch = smem + SM_WB + (BUF) * WBUF;                               \
        _Pragma("unroll")                                                            \
        for (int z = 0; z < 16; z++) (ACC)[z] = 0.0f;                                \
        uint4 nh0 = *(const uint4*)(wch + lane * 16);                                \
        uint4 nh1 = *(const uint4*)(wch + 512 + lane * 16);                          \
        _Pragma("unroll")                                                            \
        for (int kk = 0; kk < 12; kk++) {                                            \
            uint4 ch0 = nh0, ch1 = nh1;                                              \
            if (kk < 11) {                                                           \
                int kn = kk + 1;                                                     \
                int o = (kn >= 6) * 6144 + (kn - (kn >= 6) * 6) * 1024 + lane * 16;  \
                nh0 = *(const uint4*)(wch + o);                                      \
                nh1 = *(const uint4*)(wch + o + 512);                                \
            }                                                                        \
            mma16816h((ACC) + 0,  AH[kk], ch0.x, ch0.y);                             \
            mma16816h((ACC) + 4,  AH[kk], ch0.z, ch0.w);                             \
            mma16816h((ACC) + 8,  AH[kk], ch1.x, ch1.y);                             \
            mma16816h((ACC) + 12, AH[kk], ch1.z, ch1.w);                             \
        }                                                                            \
    }

    // Prefetch full chunk NC (12288B) into buffer NC&1: 96B per thread
    #define PREFETCH_W(NC)                                                           \
    {                                                                                \
        uint32_t dst = sbase + SM_WB + ((NC) & 1) * WBUF;                            \
        const char* srcW = (const char*)g_WF + (NC) * WCHUNK;                        \
        _Pragma("unroll")                                                            \
        for (int i = 0; i < 6; i++) {                                                \
            int o = tid * 16 + i * 2048;                                             \
            cpasync16(dst + o, srcW + o);                                            \
        }                                                                            \
        CP_COMMIT();                                                                 \
    }

    for (int t = 0; t < T_STEPS; t++) {
        const int act = mask[(size_t)t * N_NODES + node];

        // emb rebuild (warp-private rows), packed fp16 stores
        {
            float2 xy = ((const float2*)nodes)[(size_t)t * N_NODES + base + erow];
            #pragma unroll 4
            for (int i = 0; i < 16; i++) {
                int k = ekb + 2 * i;
                float e0 = fmaxf(fmaf(xy.x, sWe[k], fmaf(xy.y, sWe[64 + k], sBe[k])), 0.0f);
                float e1 = fmaxf(fmaf(xy.x, sWe[k + 1], fmaf(xy.y, sWe[64 + k + 1], sBe[k + 1])), 0.0f);
                uint32_t pk = (uint32_t)__half_as_ushort(__float2half_rn(e0))
                            | ((uint32_t)__half_as_ushort(__float2half_rn(e1)) << 16);
                *(uint32_t*)(smem + SM_XH + erow * XPITCH + 2 * k) = pk;
            }
        }
        __syncwarp();

        PREFETCH_W(0)

        // load A fragments once per step (register-resident X, single fp16)
        uint32_t AH[12][4];
        #pragma unroll
        for (int kk = 0; kk < 12; kk++)
            ldsm4(AH[kk][0], AH[kk][1], AH[kk][2], AH[kk][3], xhBase + aoff + kk * 32);

        float oacc[5] = {0.f, 0.f, 0.f, 0.f, 0.f};
        float accA[16], accB[16];

        // pipelined chunk loop: 1 barrier per chunk, epilogue(nc-1) under MMA(nc)
        for (int nc2 = 0; nc2 < NCHUNKS; nc2 += 2) {
            CP_WAIT0();
            __syncthreads();
            if (nc2 + 1 < NCHUNKS) PREFETCH_W(nc2 + 1)
            MMA_CHUNK(accA, 0)
            if (nc2 > 0) EPILOGUE(accB, nc2 - 1)
            CP_WAIT0();
            __syncthreads();
            if (nc2 + 2 < NCHUNKS) PREFETCH_W(nc2 + 2)
            MMA_CHUNK(accB, 1)
            EPILOGUE(accA, nc2)
        }
        EPILOGUE(accB, NCHUNKS - 1)

        // combine j-halves and write out
        float comb[5];
        #pragma unroll
        for (int z = 0; z < 5; z++)
            comb[z] = oacc[z] + __shfl_xor_sync(0xffffffffu, oacc[z], 2);
        if (p4 < 2) {
            float* op = out + ((size_t)t * N_NODES + node) * 5;
            if (act) {
                op[0] = comb[0] + sBout[0];
                op[1] = comb[1] + sBout[1];
                op[2] = comb[2] + sBout[2];
                op[3] = comb[3] + sBout[3];
                op[4] = comb[4] + sBout[4];
            } else {
                op[0] = 0.f; op[1] = 0.f; op[2] = 0.f; op[3] = 0.f; op[4] = 0.f;
            }
        }
    }

    // ---- final h (exact hi+lo reconstruction), c ----
    __syncthreads();
    for (int idx = tid; idx < TILE_N * DH; idx += NTHREADS) {
        int n = idx >> 7, j = idx & 127;
        float hv = __half2float(__ushort_as_half(
                       *(unsigned short*)(smem + SM_XH + n * XPITCH + 128 + 2 * j)))
                 + __half2float(__ushort_as_half(
                       *(unsigned short*)(smem + SM_HL + n * HLPITCH + 2 * j)));
        hfin[(size_t)(base + n) * DH + j] = hv;
        cfin[(size_t)(base + n) * DH + j] = sc[n * CPITCH + j];
    }
}

extern "C" void kernel_launch(void* const* d_in, const int* in_sizes, int n_in,
                              void* d_out, int out_size) {
    const float* nodes = (const float*)d_in[0];
    const int* mask    = (const int*)d_in[1];
    const float* h0    = (const float*)d_in[2];
    const float* c0    = (const float*)d_in[3];
    const float* We    = (const float*)d_in[4];
    const float* be    = (const float*)d_in[5];
    const float* Wih   = (const float*)d_in[6];
    const float* bih   = (const float*)d_in[7];
    const float* Whh   = (const float*)d_in[8];
    const float* bhh   = (const float*)d_in[9];
    const float* Wout  = (const float*)d_in[10];
    const float* bout  = (const float*)d_in[11];

    float* out  = (float*)d_out;
    float* hfin = out + (size_t)T_STEPS * N_NODES * 5;
    float* cfin = hfin + (size_t)N_NODES * DH;

    prep_frag<<<(32 * 6 * 2 * 32 * 4 + 255) / 256, 256>>>(Wih, Whh);

    cudaFuncSetAttribute(vlstm_mma, cudaFuncAttributeMaxDynamicSharedMemorySize, SMEM_TOTAL);
    vlstm_mma<<<NBLOCKS, NTHREADS, SMEM_TOTAL>>>(
        nodes, mask, h0, c0, We, be, bih, bhh, Wout, bout, out, hfin, cfin);
}